// round 8
// baseline (speedup 1.0000x reference)
#include <cuda_runtime.h>
#include <cstdint>
#include <cstddef>

// Problem constants (fixed by the reference).
#define B_ROWS 32768
#define NDIM   64
#define HDIM   256
#define OFFDIM 2016   // 64*63/2

// ---------------------------------------------------------------------------
// Device scratch (__device__ globals; no allocation APIs allowed).
// ---------------------------------------------------------------------------
__device__ float g_h1[(size_t)B_ROWS * HDIM];
__device__ float g_h2[(size_t)B_ROWS * HDIM];
__device__ float g_h3[(size_t)B_ROWS * HDIM];
__device__ float g_diag[(size_t)B_ROWS * NDIM];
__device__ float g_off[(size_t)B_ROWS * OFFDIM];

// Transposed + tf32-split weights: Wt[n][k] (K contiguous => coalesced loads)
#define WT_D1 0
#define WT_D2 16384
#define WT_DO 81920
#define WT_O1 98304
#define WT_O2 114688
#define WT_OO 180224
#define WT_TOT 696320
__device__ uint32_t g_wth[WT_TOT];
__device__ uint32_t g_wtl[WT_TOT];

// ---------------------------------------------------------------------------
// tf32 hi/lo split (3xtf32 emulation of fp32: hi*hi + lo*hi + hi*lo, ~eps^2)
// ---------------------------------------------------------------------------
__device__ __forceinline__ uint32_t f2tf32(float x) {
    uint32_t r;
    asm("cvt.rna.tf32.f32 %0, %1;" : "=r"(r) : "f"(x));
    return r;
}
__device__ __forceinline__ void split_tf32(float x, uint32_t& hi, uint32_t& lo) {
    hi = f2tf32(x);
    lo = f2tf32(x - __uint_as_float(hi));
}

// m16n8k8 tf32 MMA (sm_80+ baseline; tensor pipe).
__device__ __forceinline__ void mma8(float* d, const uint32_t* a,
                                     const uint32_t* b) {
    asm volatile(
        "mma.sync.aligned.m16n8k8.row.col.f32.tf32.tf32.f32 "
        "{%0,%1,%2,%3}, {%4,%5,%6,%7}, {%8,%9}, {%0,%1,%2,%3};"
        : "+f"(d[0]), "+f"(d[1]), "+f"(d[2]), "+f"(d[3])
        : "r"(a[0]), "r"(a[1]), "r"(a[2]), "r"(a[3]), "r"(b[0]), "r"(b[1]));
}

// ldmatrix x4 on tf32 data: 8x16B tiles -> mma fragments directly with
// [row][k] 128B-row swizzled smem.
__device__ __forceinline__ void ldsm4(uint32_t* r, uint32_t addr) {
    asm volatile(
        "ldmatrix.sync.aligned.m8n8.x4.shared.b16 {%0,%1,%2,%3}, [%4];"
        : "=r"(r[0]), "=r"(r[1]), "=r"(r[2]), "=r"(r[3]) : "r"(addr));
}

__device__ __forceinline__ uint32_t smem_u32(const void* p) {
    uint32_t a;
    asm("{ .reg .u64 t; cvta.to.shared.u64 t, %1; cvt.u32.u64 %0, t; }"
        : "=r"(a) : "l"(p));
    return a;
}

enum { EPI_TANH = 0, EPI_BIAS = 1, EPI_DIAG = 2 };

// ---------------------------------------------------------------------------
// Single prep launch: all 6 weights, W[K,N] fp32 -> Wt_hi/Wt_lo[N,K] tf32.
// ---------------------------------------------------------------------------
__global__ void prep_all(const float* __restrict__ Wd1, const float* __restrict__ Wd2,
                         const float* __restrict__ Wdo, const float* __restrict__ Wo1,
                         const float* __restrict__ Wo2, const float* __restrict__ Woo,
                         uint32_t* __restrict__ th, uint32_t* __restrict__ tl) {
    int idx = blockIdx.x * 256 + threadIdx.x;
    const float* W;
    int K, N, base, local;
    if (idx < 16384)       { W = Wd1; K = 64;  N = 256;  base = WT_D1; local = idx; }
    else if (idx < 81920)  { W = Wd2; K = 256; N = 256;  base = WT_D2; local = idx - 16384; }
    else if (idx < 98304)  { W = Wdo; K = 256; N = 64;   base = WT_DO; local = idx - 81920; }
    else if (idx < 114688) { W = Wo1; K = 64;  N = 256;  base = WT_O1; local = idx - 98304; }
    else if (idx < 180224) { W = Wo2; K = 256; N = 256;  base = WT_O2; local = idx - 114688; }
    else if (idx < 696320) { W = Woo; K = 256; N = 2016; base = WT_OO; local = idx - 180224; }
    else return;
    int k = local / N, n = local % N;
    uint32_t hi, lo;
    split_tf32(W[(size_t)k * N + n], hi, lo);
    th[(size_t)base + (size_t)n * K + k] = hi;
    tl[(size_t)base + (size_t)n * K + k] = lo;
}

// ---------------------------------------------------------------------------
// tf32 mma.sync GEMM, 3xtf32. BM=128, BN=128, BK=32; 512 threads = 16 warps
// as 4(M)x4(N), warp tile 32x32 (occ 25%: 4 warps/SMSP to hide ldsm/LDS
// latency — the R6-measured limiter). ldmatrix fragments from SW128-swizzled
// [row][k] smem; LDG(t+1) before chunk-t MMAs, split+STS after.
//
// smem: 2 bufs x 64KB (AH|AL|BH|BL, 16KB each) = 128KB. Epilogue staging
// [128][132] fp32 (67.6KB) reuses the buffers.
// ---------------------------------------------------------------------------
#define BUFB 65536
#define SOFF_AL 16384
#define SOFF_BH 32768
#define SOFF_BL 49152
#define LDP 132
#define GEMM_SMEM (2 * BUFB)
#define NTHR 512

template <int EPI>
__global__ void __launch_bounds__(NTHR, 1)
gemm_mma(const float* __restrict__ A, const uint32_t* __restrict__ Bth,
         const uint32_t* __restrict__ Btl, const float* __restrict__ bias,
         float* __restrict__ C, int K, int N, int ldc,
         const float* __restrict__ xin, const float* __restrict__ dmin) {
    extern __shared__ char smem[];
    const uint32_t sbase = smem_u32(smem);
    const int tid = threadIdx.x;
    const int wid = tid >> 5, lane = tid & 31;
    const int g = lane >> 2, tig = lane & 3;
    const int warpM = (wid >> 2) * 32;
    const int warpN = (wid & 3) * 32;
    const int m0 = blockIdx.y * 128;
    const int n0 = blockIdx.x * 128;

    // ldmatrix lane constants. 16B-col swizzle: col' = col ^ (row & 7).
    const uint32_t xorv = lane & 7;
    const int aRow = (lane & 7) + ((lane >> 3) & 1) * 8;  // +8 rows tiles 1,3
    const int aKq  = lane >> 4;                           // +1 col tiles 2,3
    const int bRow = (lane & 7) + ((lane >> 4) & 1) * 8;  // +8 n tiles 2,3
    const int bKq  = (lane >> 3) & 1;                     // +1 col tiles 1,3

    float d[2][4][4];
#pragma unroll
    for (int mt = 0; mt < 2; mt++)
#pragma unroll
        for (int nt = 0; nt < 4; nt++)
#pragma unroll
            for (int j = 0; j < 4; j++) d[mt][nt][j] = 0.f;

    float4 sa[2];
    uint4 sbh[2], sbl[2];

    auto ldg_stage = [&](int t) {
        const float* Ab = A + (size_t)m0 * K + t * 32;
#pragma unroll
        for (int i = 0; i < 2; i++) {
            int idx = tid + i * NTHR, row = idx >> 3, kq = idx & 7;
            sa[i] = *reinterpret_cast<const float4*>(Ab + (size_t)row * K + kq * 4);
        }
#pragma unroll
        for (int i = 0; i < 2; i++) {
            int idx = tid + i * NTHR, row = idx >> 3, kq = idx & 7;
            if (n0 + row < N) {
                sbh[i] = *reinterpret_cast<const uint4*>(
                    Bth + (size_t)(n0 + row) * K + t * 32 + kq * 4);
                sbl[i] = *reinterpret_cast<const uint4*>(
                    Btl + (size_t)(n0 + row) * K + t * 32 + kq * 4);
            } else {
                sbh[i] = make_uint4(0u, 0u, 0u, 0u);
                sbl[i] = make_uint4(0u, 0u, 0u, 0u);
            }
        }
    };

    auto split_sts = [&](int b) {
        char* buf = smem + b * BUFB;
#pragma unroll
        for (int i = 0; i < 2; i++) {
            int idx = tid + i * NTHR, row = idx >> 3, kq = idx & 7;
            uint32_t off = (uint32_t)row * 128 + (((uint32_t)kq ^ (row & 7)) << 4);
            uint4 h, l;
            split_tf32(sa[i].x, h.x, l.x);
            split_tf32(sa[i].y, h.y, l.y);
            split_tf32(sa[i].z, h.z, l.z);
            split_tf32(sa[i].w, h.w, l.w);
            *reinterpret_cast<uint4*>(buf + off)           = h;
            *reinterpret_cast<uint4*>(buf + SOFF_AL + off) = l;
        }
#pragma unroll
        for (int i = 0; i < 2; i++) {
            int idx = tid + i * NTHR, row = idx >> 3, kq = idx & 7;
            uint32_t off = (uint32_t)row * 128 + (((uint32_t)kq ^ (row & 7)) << 4);
            *reinterpret_cast<uint4*>(buf + SOFF_BH + off) = sbh[i];
            *reinterpret_cast<uint4*>(buf + SOFF_BL + off) = sbl[i];
        }
    };

    auto mma_chunk = [&](int b) {
        const uint32_t AH = sbase + b * BUFB;
        const uint32_t AL = AH + SOFF_AL;
        const uint32_t BH = AH + SOFF_BH;
        const uint32_t BL = AH + SOFF_BL;
#pragma unroll
        for (int ks = 0; ks < 4; ks++) {
            const uint32_t acol = (((uint32_t)(ks * 2 + aKq)) ^ xorv) << 4;
            const uint32_t bcol = (((uint32_t)(ks * 2 + bKq)) ^ xorv) << 4;
            uint32_t ah[2][4], al[2][4];
#pragma unroll
            for (int mt = 0; mt < 2; mt++) {
                uint32_t ro = (uint32_t)(warpM + mt * 16 + aRow) * 128 + acol;
                ldsm4(ah[mt], AH + ro);
                ldsm4(al[mt], AL + ro);
            }
#pragma unroll
            for (int p = 0; p < 2; p++) {
                uint32_t bh[4], bl[4];
                uint32_t ro = (uint32_t)(warpN + p * 16 + bRow) * 128 + bcol;
                ldsm4(bh, BH + ro);
                ldsm4(bl, BL + ro);
#pragma unroll
                for (int q = 0; q < 2; q++) {
                    const int nt = p * 2 + q;
#pragma unroll
                    for (int mt = 0; mt < 2; mt++) {
                        mma8(d[mt][nt], ah[mt], bh + q * 2);  // hi*hi
                        mma8(d[mt][nt], al[mt], bh + q * 2);  // lo*hi
                        mma8(d[mt][nt], ah[mt], bl + q * 2);  // hi*lo
                    }
                }
            }
        }
    };

    const int nT = K >> 5;
    ldg_stage(0);
    split_sts(0);
    __syncthreads();
    for (int t = 0; t < nT; t++) {
        if (t + 1 < nT) ldg_stage(t + 1);   // LDG only; consumed after MMAs
        mma_chunk(t & 1);                   // tensor work hides LDG latency
        if (t + 1 < nT) split_sts((t + 1) & 1);
        __syncthreads();
    }

    // Epilogue: stage D in smem (reuse buffers), coalesced float4 STG.
    float* stg = reinterpret_cast<float*>(smem);  // [128][LDP]
#pragma unroll
    for (int mt = 0; mt < 2; mt++)
#pragma unroll
        for (int nt = 0; nt < 4; nt++) {
            int r = warpM + mt * 16 + g;
            int c = warpN + nt * 8 + tig * 2;
            stg[r * LDP + c]           = d[mt][nt][0];
            stg[r * LDP + c + 1]       = d[mt][nt][1];
            stg[(r + 8) * LDP + c]     = d[mt][nt][2];
            stg[(r + 8) * LDP + c + 1] = d[mt][nt][3];
        }
    __syncthreads();
    {
        const int r  = tid >> 2;
        const int cb = (tid & 3) * 32;
#pragma unroll
        for (int j = 0; j < 8; j++) {
            int c = cb + j * 4;
            if (n0 + c < N) {  // N, c multiples of 4 -> whole float4 valid
                const float* s = stg + r * LDP + c;
                float v[4] = {s[0], s[1], s[2], s[3]};
#pragma unroll
                for (int q = 0; q < 4; q++) {
                    float val = v[q] + bias[n0 + c + q];
                    if (EPI == EPI_TANH) {
                        val = tanhf(val);
                    } else if (EPI == EPI_DIAG) {
                        float dd = fmaxf(val, 0.f) + dmin[n0 + c + q];
                        val = dd * xin[(size_t)(m0 + r) * NDIM + n0 + c + q];
                    }
                    v[q] = val;
                }
                *reinterpret_cast<float4*>(C + (size_t)(m0 + r) * ldc + n0 + c) =
                    make_float4(v[0], v[1], v[2], v[3]);
            }
        }
    }
}

// ---------------------------------------------------------------------------
// Final: out = L (L^T x) per batch row; L from (off, diag).
// ---------------------------------------------------------------------------
__global__ void __launch_bounds__(256)
final_kernel(const float* __restrict__ off, const float* __restrict__ diag,
             const float* __restrict__ x, float* __restrict__ out) {
    __shared__ float soff[4][OFFDIM];
    __shared__ float sx[4][NDIM];
    __shared__ float sd[4][NDIM];
    __shared__ float sv[4][NDIM];

    const int r    = threadIdx.x >> 6;
    const int lane = threadIdx.x & 63;
    const size_t row = (size_t)blockIdx.x * 4 + r;

    sx[r][lane] = x[row * NDIM + lane];
    sd[r][lane] = diag[row * NDIM + lane];
    const float* offr = off + row * OFFDIM;
    for (int i = lane; i < OFFDIM; i += 64) soff[r][i] = offr[i];
    __syncthreads();

    float v = sd[r][lane] * sx[r][lane];
    for (int i = lane + 1; i < NDIM; i++)
        v += soff[r][i * (i - 1) / 2 + lane] * sx[r][i];
    sv[r][lane] = v;
    __syncthreads();

    float o = sd[r][lane] * v;
    const int base = lane * (lane - 1) / 2;
    for (int j = 0; j < lane; j++) o += soff[r][base + j] * sv[r][j];
    out[row * NDIM + lane] = o;
}

// ---------------------------------------------------------------------------
// Launch. Inputs: x, Wd1, bd1, Wd2, bd2, Wdo, bdo, Wo1, bo1, Wo2, bo2,
//                 Woo, boo, damp_min
// Launch order keeps the Woo GEMM 6th so ncu (-s 5 -c 1) profiles it.
// ---------------------------------------------------------------------------
extern "C" void kernel_launch(void* const* d_in, const int* in_sizes, int n_in,
                              void* d_out, int out_size) {
    const float* x    = (const float*)d_in[0];
    const float* Wd1  = (const float*)d_in[1];
    const float* bd1  = (const float*)d_in[2];
    const float* Wd2  = (const float*)d_in[3];
    const float* bd2  = (const float*)d_in[4];
    const float* Wdo  = (const float*)d_in[5];
    const float* bdo  = (const float*)d_in[6];
    const float* Wo1  = (const float*)d_in[7];
    const float* bo1  = (const float*)d_in[8];
    const float* Wo2  = (const float*)d_in[9];
    const float* bo2  = (const float*)d_in[10];
    const float* Woo  = (const float*)d_in[11];
    const float* boo  = (const float*)d_in[12];
    const float* dmin = (const float*)d_in[13];
    float* out = (float*)d_out;

    float *h1, *h2, *h3, *dg, *off;
    uint32_t *wth, *wtl;
    cudaGetSymbolAddress((void**)&h1,  g_h1);
    cudaGetSymbolAddress((void**)&h2,  g_h2);
    cudaGetSymbolAddress((void**)&h3,  g_h3);
    cudaGetSymbolAddress((void**)&dg,  g_diag);
    cudaGetSymbolAddress((void**)&off, g_off);
    cudaGetSymbolAddress((void**)&wth, g_wth);
    cudaGetSymbolAddress((void**)&wtl, g_wtl);

    cudaFuncSetAttribute(gemm_mma<EPI_TANH>,
                         cudaFuncAttributeMaxDynamicSharedMemorySize, GEMM_SMEM);
    cudaFuncSetAttribute(gemm_mma<EPI_BIAS>,
                         cudaFuncAttributeMaxDynamicSharedMemorySize, GEMM_SMEM);
    cudaFuncSetAttribute(gemm_mma<EPI_DIAG>,
                         cudaFuncAttributeMaxDynamicSharedMemorySize, GEMM_SMEM);

    // 1: weight prep (transpose + tf32 split), single launch
    prep_all<<<(WT_TOT + 255) / 256, 256>>>(Wd1, Wd2, Wdo, Wo1, Wo2, Woo, wth, wtl);

    const int MB = B_ROWS / 128;  // 256 m-tiles
    // 2-3: diag hidden layers
    gemm_mma<EPI_TANH><<<dim3(2, MB), NTHR, GEMM_SMEM>>>(
        x, wth + WT_D1, wtl + WT_D1, bd1, h1, NDIM, HDIM, HDIM, nullptr, nullptr);
    gemm_mma<EPI_TANH><<<dim3(2, MB), NTHR, GEMM_SMEM>>>(
        h1, wth + WT_D2, wtl + WT_D2, bd2, h2, HDIM, HDIM, HDIM, nullptr, nullptr);
    // 4-5: off hidden layers
    gemm_mma<EPI_TANH><<<dim3(2, MB), NTHR, GEMM_SMEM>>>(
        x, wth + WT_O1, wtl + WT_O1, bo1, h1, NDIM, HDIM, HDIM, nullptr, nullptr);
    gemm_mma<EPI_TANH><<<dim3(2, MB), NTHR, GEMM_SMEM>>>(
        h1, wth + WT_O2, wtl + WT_O2, bo2, h3, HDIM, HDIM, HDIM, nullptr, nullptr);
    // 6: dominant Woo GEMM (profiled by ncu)
    gemm_mma<EPI_BIAS><<<dim3(16, MB), NTHR, GEMM_SMEM>>>(
        h3, wth + WT_OO, wtl + WT_OO, boo, off, HDIM, OFFDIM, OFFDIM, nullptr, nullptr);
    // 7: diag output
    gemm_mma<EPI_DIAG><<<dim3(1, MB), NTHR, GEMM_SMEM>>>(
        h2, wth + WT_DO, wtl + WT_DO, bdo, dg, HDIM, NDIM, NDIM, x, dmin);
    // 8: L (L^T x)
    final_kernel<<<B_ROWS / 4, 256>>>(off, dg, x, out);
}

// round 10
// speedup vs baseline: 1.0391x; 1.0391x over previous
#include <cuda_runtime.h>
#include <cuda_bf16.h>
#include <cstdint>
#include <cstddef>

// Problem constants (fixed by the reference).
#define B_ROWS 32768
#define NDIM   64
#define HDIM   256
#define OFFDIM 2016   // 64*63/2

// ---------------------------------------------------------------------------
// Device scratch (__device__ globals; no allocation APIs allowed).
// ---------------------------------------------------------------------------
__device__ float g_h1[(size_t)B_ROWS * HDIM];
__device__ float g_h2[(size_t)B_ROWS * HDIM];
__device__ float g_h3[(size_t)B_ROWS * HDIM];
__device__ float g_diag[(size_t)B_ROWS * NDIM];
__device__ float g_off[(size_t)B_ROWS * OFFDIM];

// Transposed + bf16-split weights: Wt[n][k] (K contiguous => coalesced loads)
#define WT_D1 0
#define WT_D2 16384
#define WT_DO 81920
#define WT_O1 98304
#define WT_O2 114688
#define WT_OO 180224
#define WT_TOT 696320
__device__ __nv_bfloat16 g_wth[WT_TOT];
__device__ __nv_bfloat16 g_wtl[WT_TOT];

// ---------------------------------------------------------------------------
// bf16 helpers. bf16x3: x ~= hi + lo; x*y ~= hi*hi + lo*hi + hi*lo
// (drops lo*lo ~ 2^-18 |x||y|; fp32 accumulate).
// ---------------------------------------------------------------------------
__device__ __forceinline__ uint32_t bf16x2_rn(float klo, float khi) {
    uint32_t r;  // low half <- klo (lower k index), high half <- khi
    asm("cvt.rn.bf16x2.f32 %0, %1, %2;" : "=r"(r) : "f"(khi), "f"(klo));
    return r;
}

// m16n8k16 bf16 MMA (sm_80+ baseline; tensor pipe). fp32 accumulators.
__device__ __forceinline__ void mma16(float* d, const uint32_t* a,
                                      const uint32_t* b) {
    asm volatile(
        "mma.sync.aligned.m16n8k16.row.col.f32.bf16.bf16.f32 "
        "{%0,%1,%2,%3}, {%4,%5,%6,%7}, {%8,%9}, {%0,%1,%2,%3};"
        : "+f"(d[0]), "+f"(d[1]), "+f"(d[2]), "+f"(d[3])
        : "r"(a[0]), "r"(a[1]), "r"(a[2]), "r"(a[3]), "r"(b[0]), "r"(b[1]));
}

// ldmatrix x4: four 8x16B tiles -> one u32/lane each; with [row][k-16B-cols]
// swizzled smem this yields m16n8k16 bf16 fragments directly.
__device__ __forceinline__ void ldsm4(uint32_t* r, uint32_t addr) {
    asm volatile(
        "ldmatrix.sync.aligned.m8n8.x4.shared.b16 {%0,%1,%2,%3}, [%4];"
        : "=r"(r[0]), "=r"(r[1]), "=r"(r[2]), "=r"(r[3]) : "r"(addr));
}

__device__ __forceinline__ uint32_t smem_u32(const void* p) {
    uint32_t a;
    asm("{ .reg .u64 t; cvta.to.shared.u64 t, %1; cvt.u32.u64 %0, t; }"
        : "=r"(a) : "l"(p));
    return a;
}

enum { EPI_TANH = 0, EPI_BIAS = 1, EPI_DIAG = 2 };

// ---------------------------------------------------------------------------
// Single prep launch: all 6 weights, W[K,N] fp32 -> Wt_hi/Wt_lo[N,K] bf16.
// ---------------------------------------------------------------------------
__global__ void prep_all(const float* __restrict__ Wd1, const float* __restrict__ Wd2,
                         const float* __restrict__ Wdo, const float* __restrict__ Wo1,
                         const float* __restrict__ Wo2, const float* __restrict__ Woo,
                         __nv_bfloat16* __restrict__ th,
                         __nv_bfloat16* __restrict__ tl) {
    int idx = blockIdx.x * 256 + threadIdx.x;
    const float* W;
    int K, N, base, local;
    if (idx < 16384)       { W = Wd1; K = 64;  N = 256;  base = WT_D1; local = idx; }
    else if (idx < 81920)  { W = Wd2; K = 256; N = 256;  base = WT_D2; local = idx - 16384; }
    else if (idx < 98304)  { W = Wdo; K = 256; N = 64;   base = WT_DO; local = idx - 81920; }
    else if (idx < 114688) { W = Wo1; K = 64;  N = 256;  base = WT_O1; local = idx - 98304; }
    else if (idx < 180224) { W = Wo2; K = 256; N = 256;  base = WT_O2; local = idx - 114688; }
    else if (idx < 696320) { W = Woo; K = 256; N = 2016; base = WT_OO; local = idx - 180224; }
    else return;
    int k = local / N, n = local % N;
    float w = W[(size_t)k * N + n];
    __nv_bfloat16 hb = __float2bfloat16_rn(w);
    __nv_bfloat16 lb = __float2bfloat16_rn(w - __bfloat162float(hb));
    th[(size_t)base + (size_t)n * K + k] = hb;
    tl[(size_t)base + (size_t)n * K + k] = lb;
}

// ---------------------------------------------------------------------------
// bf16x3 mma.sync GEMM: C[M,N] = epi(A[M,K] @ W[K,N] + bias).
// BM=128, BN=128, BK=32; 512 threads = 16 warps (4Mx4N), warp tile 32x32.
// Smem row layout per operand row: [hi 32 bf16 (64B) | lo 32 bf16 (64B)]
// = 128B rows with 16B-col XOR swizzle -> conflict-free ldmatrix + STS.
// m16n8k16 halves both smem bytes/MAC and MMA instructions vs tf32x3
// (R8-measured limiter: smem crossbar at ~2560 cyc/chunk vs 1536 tensor).
//
// smem: 2 bufs x (A 16KB | B 16KB) = 64KB; epilogue staging [128][132] fp32
// (67.6KB) overlays everything -> dyn smem 69632B.
// ---------------------------------------------------------------------------
#define BUFB 32768
#define SOFF_B 16384
#define LDP 132
#define GEMM_SMEM 69632
#define NTHR 512

template <int EPI>
__global__ void __launch_bounds__(NTHR, 1)
gemm_mma(const float* __restrict__ A, const __nv_bfloat16* __restrict__ Bth,
         const __nv_bfloat16* __restrict__ Btl, const float* __restrict__ bias,
         float* __restrict__ C, int K, int N, int ldc,
         const float* __restrict__ xin, const float* __restrict__ dmin) {
    extern __shared__ char smem[];
    const uint32_t sbase = smem_u32(smem);
    const int tid = threadIdx.x;
    const int wid = tid >> 5, lane = tid & 31;
    const int g = lane >> 2, tig = lane & 3;
    const int warpM = (wid >> 2) * 32;
    const int warpN = (wid & 3) * 32;
    const int m0 = blockIdx.y * 128;
    const int n0 = blockIdx.x * 128;

    // Staging thread map: row fastest within warp -> conflict-free STS.
    const int srow = (tid & 7) | ((tid >> 5) << 3);  // 0..127
    const int sqq  = (tid >> 3) & 3;                 // 16B col 0..3

    // ldmatrix lane constants (k16 tile set maps onto same constants).
    const uint32_t xorv = lane & 7;
    const int aRow = (lane & 7) + ((lane >> 3) & 1) * 8;
    const int aKq  = lane >> 4;
    const int bRow = (lane & 7) + ((lane >> 4) & 1) * 8;
    const int bKq  = (lane >> 3) & 1;

    float d[2][4][4];
#pragma unroll
    for (int mt = 0; mt < 2; mt++)
#pragma unroll
        for (int nt = 0; nt < 4; nt++)
#pragma unroll
            for (int j = 0; j < 4; j++) d[mt][nt][j] = 0.f;

    float4 sa0, sa1;   // 8 consecutive k fp32 of A
    uint4 sbh, sbl;    // 8 consecutive k bf16 hi/lo of B

    auto ldg_stage = [&](int t) {
        const float* ap = A + (size_t)(m0 + srow) * K + t * 32 + sqq * 8;
        sa0 = *reinterpret_cast<const float4*>(ap);
        sa1 = *reinterpret_cast<const float4*>(ap + 4);
        if (n0 + srow < N) {
            size_t bo = (size_t)(n0 + srow) * K + t * 32 + sqq * 8;
            sbh = *reinterpret_cast<const uint4*>(Bth + bo);
            sbl = *reinterpret_cast<const uint4*>(Btl + bo);
        } else {
            sbh = make_uint4(0u, 0u, 0u, 0u);
            sbl = make_uint4(0u, 0u, 0u, 0u);
        }
    };

    auto split_sts = [&](int b) {
        char* buf = smem + b * BUFB;
        // A: 8 fp32 -> 8 bf16 hi (16B) + 8 bf16 lo (16B)
        float f[8] = {sa0.x, sa0.y, sa0.z, sa0.w, sa1.x, sa1.y, sa1.z, sa1.w};
        float rf[8];
#pragma unroll
        for (int j = 0; j < 8; j++)
            rf[j] = f[j] - __bfloat162float(__float2bfloat16_rn(f[j]));
        uint4 h, l;
        h.x = bf16x2_rn(f[0], f[1]);   h.y = bf16x2_rn(f[2], f[3]);
        h.z = bf16x2_rn(f[4], f[5]);   h.w = bf16x2_rn(f[6], f[7]);
        l.x = bf16x2_rn(rf[0], rf[1]); l.y = bf16x2_rn(rf[2], rf[3]);
        l.z = bf16x2_rn(rf[4], rf[5]); l.w = bf16x2_rn(rf[6], rf[7]);
        const uint32_t rb = (uint32_t)srow * 128;
        const uint32_t r7 = srow & 7;
        *reinterpret_cast<uint4*>(buf + rb + (((uint32_t)sqq ^ r7) << 4))       = h;
        *reinterpret_cast<uint4*>(buf + rb + (((uint32_t)(4 + sqq) ^ r7) << 4)) = l;
        // B: store pre-split bf16 directly
        *reinterpret_cast<uint4*>(buf + SOFF_B + rb + (((uint32_t)sqq ^ r7) << 4))       = sbh;
        *reinterpret_cast<uint4*>(buf + SOFF_B + rb + (((uint32_t)(4 + sqq) ^ r7) << 4)) = sbl;
    };

    auto mma_chunk = [&](int b) {
        const uint32_t Ab = sbase + b * BUFB;
        const uint32_t Bb = Ab + SOFF_B;
#pragma unroll
        for (int ks = 0; ks < 2; ks++) {  // 2 x k16 per 32-k chunk
            const uint32_t ach = (((uint32_t)(ks * 2 + aKq)) ^ xorv) << 4;
            const uint32_t acl = (((uint32_t)(4 + ks * 2 + aKq)) ^ xorv) << 4;
            const uint32_t bch = (((uint32_t)(ks * 2 + bKq)) ^ xorv) << 4;
            const uint32_t bcl = (((uint32_t)(4 + ks * 2 + bKq)) ^ xorv) << 4;
            uint32_t ah[2][4], al[2][4];
#pragma unroll
            for (int mt = 0; mt < 2; mt++) {
                uint32_t ro = (uint32_t)(warpM + mt * 16 + aRow) * 128;
                ldsm4(ah[mt], Ab + ro + ach);
                ldsm4(al[mt], Ab + ro + acl);
            }
#pragma unroll
            for (int p = 0; p < 2; p++) {
                uint32_t bh[4], bl[4];
                uint32_t ro = (uint32_t)(warpN + p * 16 + bRow) * 128;
                ldsm4(bh, Bb + ro + bch);
                ldsm4(bl, Bb + ro + bcl);
#pragma unroll
                for (int q = 0; q < 2; q++) {
                    const int nt = p * 2 + q;
#pragma unroll
                    for (int mt = 0; mt < 2; mt++) {
                        mma16(d[mt][nt], ah[mt], bh + q * 2);  // hi*hi
                        mma16(d[mt][nt], al[mt], bh + q * 2);  // lo*hi
                        mma16(d[mt][nt], ah[mt], bl + q * 2);  // hi*lo
                    }
                }
            }
        }
    };

    const int nT = K >> 5;
    ldg_stage(0);
    split_sts(0);
    __syncthreads();
    for (int t = 0; t < nT; t++) {
        if (t + 1 < nT) ldg_stage(t + 1);   // LDG only; consumed after MMAs
        mma_chunk(t & 1);                   // tensor work hides LDG latency
        if (t + 1 < nT) split_sts((t + 1) & 1);
        __syncthreads();
    }

    // Epilogue: stage D in smem (overlays buffers), coalesced float4 STG.
    float* stg = reinterpret_cast<float*>(smem);  // [128][LDP]
#pragma unroll
    for (int mt = 0; mt < 2; mt++)
#pragma unroll
        for (int nt = 0; nt < 4; nt++) {
            int r = warpM + mt * 16 + g;
            int c = warpN + nt * 8 + tig * 2;
            stg[r * LDP + c]           = d[mt][nt][0];
            stg[r * LDP + c + 1]       = d[mt][nt][1];
            stg[(r + 8) * LDP + c]     = d[mt][nt][2];
            stg[(r + 8) * LDP + c + 1] = d[mt][nt][3];
        }
    __syncthreads();
    {
        const int r  = tid >> 2;
        const int cb = (tid & 3) * 32;
#pragma unroll
        for (int j = 0; j < 8; j++) {
            int c = cb + j * 4;
            if (n0 + c < N) {  // N, c multiples of 4 -> whole float4 valid
                const float* s = stg + r * LDP + c;
                float v[4] = {s[0], s[1], s[2], s[3]};
#pragma unroll
                for (int q = 0; q < 4; q++) {
                    float val = v[q] + bias[n0 + c + q];
                    if (EPI == EPI_TANH) {
                        val = tanhf(val);
                    } else if (EPI == EPI_DIAG) {
                        float dd = fmaxf(val, 0.f) + dmin[n0 + c + q];
                        val = dd * xin[(size_t)(m0 + r) * NDIM + n0 + c + q];
                    }
                    v[q] = val;
                }
                *reinterpret_cast<float4*>(C + (size_t)(m0 + r) * ldc + n0 + c) =
                    make_float4(v[0], v[1], v[2], v[3]);
            }
        }
    }
}

// ---------------------------------------------------------------------------
// Final: out = L (L^T x) per batch row; L from (off, diag).
// ---------------------------------------------------------------------------
__global__ void __launch_bounds__(256)
final_kernel(const float* __restrict__ off, const float* __restrict__ diag,
             const float* __restrict__ x, float* __restrict__ out) {
    __shared__ float soff[4][OFFDIM];
    __shared__ float sx[4][NDIM];
    __shared__ float sd[4][NDIM];
    __shared__ float sv[4][NDIM];

    const int r    = threadIdx.x >> 6;
    const int lane = threadIdx.x & 63;
    const size_t row = (size_t)blockIdx.x * 4 + r;

    sx[r][lane] = x[row * NDIM + lane];
    sd[r][lane] = diag[row * NDIM + lane];
    const float* offr = off + row * OFFDIM;
    for (int i = lane; i < OFFDIM; i += 64) soff[r][i] = offr[i];
    __syncthreads();

    float v = sd[r][lane] * sx[r][lane];
    for (int i = lane + 1; i < NDIM; i++)
        v += soff[r][i * (i - 1) / 2 + lane] * sx[r][i];
    sv[r][lane] = v;
    __syncthreads();

    float o = sd[r][lane] * v;
    const int base = lane * (lane - 1) / 2;
    for (int j = 0; j < lane; j++) o += soff[r][base + j] * sv[r][j];
    out[row * NDIM + lane] = o;
}

// ---------------------------------------------------------------------------
// Launch. Inputs: x, Wd1, bd1, Wd2, bd2, Wdo, bdo, Wo1, bo1, Wo2, bo2,
//                 Woo, boo, damp_min
// Launch order keeps the Woo GEMM 6th so ncu (-s 5 -c 1) profiles it.
// ---------------------------------------------------------------------------
extern "C" void kernel_launch(void* const* d_in, const int* in_sizes, int n_in,
                              void* d_out, int out_size) {
    const float* x    = (const float*)d_in[0];
    const float* Wd1  = (const float*)d_in[1];
    const float* bd1  = (const float*)d_in[2];
    const float* Wd2  = (const float*)d_in[3];
    const float* bd2  = (const float*)d_in[4];
    const float* Wdo  = (const float*)d_in[5];
    const float* bdo  = (const float*)d_in[6];
    const float* Wo1  = (const float*)d_in[7];
    const float* bo1  = (const float*)d_in[8];
    const float* Wo2  = (const float*)d_in[9];
    const float* bo2  = (const float*)d_in[10];
    const float* Woo  = (const float*)d_in[11];
    const float* boo  = (const float*)d_in[12];
    const float* dmin = (const float*)d_in[13];
    float* out = (float*)d_out;

    float *h1, *h2, *h3, *dg, *off;
    __nv_bfloat16 *wth, *wtl;
    cudaGetSymbolAddress((void**)&h1,  g_h1);
    cudaGetSymbolAddress((void**)&h2,  g_h2);
    cudaGetSymbolAddress((void**)&h3,  g_h3);
    cudaGetSymbolAddress((void**)&dg,  g_diag);
    cudaGetSymbolAddress((void**)&off, g_off);
    cudaGetSymbolAddress((void**)&wth, g_wth);
    cudaGetSymbolAddress((void**)&wtl, g_wtl);

    cudaFuncSetAttribute(gemm_mma<EPI_TANH>,
                         cudaFuncAttributeMaxDynamicSharedMemorySize, GEMM_SMEM);
    cudaFuncSetAttribute(gemm_mma<EPI_BIAS>,
                         cudaFuncAttributeMaxDynamicSharedMemorySize, GEMM_SMEM);
    cudaFuncSetAttribute(gemm_mma<EPI_DIAG>,
                         cudaFuncAttributeMaxDynamicSharedMemorySize, GEMM_SMEM);

    // 1: weight prep (transpose + bf16 split), single launch
    prep_all<<<(WT_TOT + 255) / 256, 256>>>(Wd1, Wd2, Wdo, Wo1, Wo2, Woo, wth, wtl);

    const int MB = B_ROWS / 128;  // 256 m-tiles
    // 2-3: diag hidden layers
    gemm_mma<EPI_TANH><<<dim3(2, MB), NTHR, GEMM_SMEM>>>(
        x, wth + WT_D1, wtl + WT_D1, bd1, h1, NDIM, HDIM, HDIM, nullptr, nullptr);
    gemm_mma<EPI_TANH><<<dim3(2, MB), NTHR, GEMM_SMEM>>>(
        h1, wth + WT_D2, wtl + WT_D2, bd2, h2, HDIM, HDIM, HDIM, nullptr, nullptr);
    // 4-5: off hidden layers
    gemm_mma<EPI_TANH><<<dim3(2, MB), NTHR, GEMM_SMEM>>>(
        x, wth + WT_O1, wtl + WT_O1, bo1, h1, NDIM, HDIM, HDIM, nullptr, nullptr);
    gemm_mma<EPI_TANH><<<dim3(2, MB), NTHR, GEMM_SMEM>>>(
        h1, wth + WT_O2, wtl + WT_O2, bo2, h3, HDIM, HDIM, HDIM, nullptr, nullptr);
    // 6: dominant Woo GEMM (profiled by ncu)
    gemm_mma<EPI_BIAS><<<dim3(16, MB), NTHR, GEMM_SMEM>>>(
        h3, wth + WT_OO, wtl + WT_OO, boo, off, HDIM, OFFDIM, OFFDIM, nullptr, nullptr);
    // 7: diag output
    gemm_mma<EPI_DIAG><<<dim3(1, MB), NTHR, GEMM_SMEM>>>(
        h2, wth + WT_DO, wtl + WT_DO, bdo, dg, HDIM, NDIM, NDIM, x, dmin);
    // 8: L (L^T x)
    final_kernel<<<B_ROWS / 4, 256>>>(off, dg, x, out);
}

// round 12
// speedup vs baseline: 1.4798x; 1.4242x over previous
#include <cuda_runtime.h>
#include <cuda_bf16.h>
#include <cstdint>
#include <cstddef>

// Problem constants (fixed by the reference).
#define B_ROWS 32768
#define NDIM   64
#define HDIM   256
#define OFFDIM 2016   // 64*63/2

// ---------------------------------------------------------------------------
// Device scratch. Activations h1/h2/h3 hold bf16 hi/lo split pairs
// (layout [M][K/32][hi 32 bf16 | lo 32 bf16] = 4 bytes/elem, same as fp32).
// diag/off stay fp32 (consumed by final_kernel).
// ---------------------------------------------------------------------------
__device__ float g_h1[(size_t)B_ROWS * HDIM];
__device__ float g_h2[(size_t)B_ROWS * HDIM];
__device__ float g_h3[(size_t)B_ROWS * HDIM];
__device__ float g_diag[(size_t)B_ROWS * NDIM];
__device__ float g_off[(size_t)B_ROWS * OFFDIM];
__device__ __nv_bfloat16 g_xs[(size_t)B_ROWS * 2 * NDIM];  // x pre-split

// Transposed + bf16-split weights, same chunked layout: per n-row,
// per 32-k group: [hi 32 | lo 32] bf16. Offsets below are in "elements"
// (1 elem = 1 hi+lo pair = 4 bytes); bf16 index = 2*offset.
#define WT_D1 0
#define WT_D2 16384
#define WT_DO 81920
#define WT_O1 98304
#define WT_O2 114688
#define WT_OO 180224
#define WT_TOT 696320
__device__ __nv_bfloat16 g_wt[(size_t)2 * WT_TOT];

// ---------------------------------------------------------------------------
// Helpers
// ---------------------------------------------------------------------------
__device__ __forceinline__ uint32_t bf16x2_rn(float klo, float khi) {
    uint32_t r;  // low half <- klo (lower index), high half <- khi
    asm("cvt.rn.bf16x2.f32 %0, %1, %2;" : "=r"(r) : "f"(khi), "f"(klo));
    return r;
}
__device__ __forceinline__ void mma16(float* d, const uint32_t* a,
                                      const uint32_t* b) {
    asm volatile(
        "mma.sync.aligned.m16n8k16.row.col.f32.bf16.bf16.f32 "
        "{%0,%1,%2,%3}, {%4,%5,%6,%7}, {%8,%9}, {%0,%1,%2,%3};"
        : "+f"(d[0]), "+f"(d[1]), "+f"(d[2]), "+f"(d[3])
        : "r"(a[0]), "r"(a[1]), "r"(a[2]), "r"(a[3]), "r"(b[0]), "r"(b[1]));
}
__device__ __forceinline__ void ldsm4(uint32_t* r, uint32_t addr) {
    asm volatile(
        "ldmatrix.sync.aligned.m8n8.x4.shared.b16 {%0,%1,%2,%3}, [%4];"
        : "=r"(r[0]), "=r"(r[1]), "=r"(r[2]), "=r"(r[3]) : "r"(addr));
}
__device__ __forceinline__ uint32_t smem_u32(const void* p) {
    uint32_t a;
    asm("{ .reg .u64 t; cvta.to.shared.u64 t, %1; cvt.u32.u64 %0, t; }"
        : "=r"(a) : "l"(p));
    return a;
}
#define CP16(d, s) \
    asm volatile("cp.async.cg.shared.global [%0], [%1], 16;" \
                 :: "r"(d), "l"(s))
#define CP16Z(d, s, sz) \
    asm volatile("cp.async.cg.shared.global [%0], [%1], 16, %2;" \
                 :: "r"(d), "l"(s), "r"(sz))
#define CP_COMMIT() asm volatile("cp.async.commit_group;" ::: "memory")
#define CP_WAIT2()  asm volatile("cp.async.wait_group 2;" ::: "memory")

enum { EPI_TANH = 0, EPI_BIAS = 1, EPI_DIAG = 2 };

// ---------------------------------------------------------------------------
// Prep: weights W[K,N] fp32 -> split-chunked Wt[n][k-chunks]; x -> g_xs.
// ---------------------------------------------------------------------------
#define PREP_TOT (WT_TOT + B_ROWS * NDIM)
__global__ void prep_all(const float* __restrict__ x,
                         const float* __restrict__ Wd1, const float* __restrict__ Wd2,
                         const float* __restrict__ Wdo, const float* __restrict__ Wo1,
                         const float* __restrict__ Wo2, const float* __restrict__ Woo,
                         __nv_bfloat16* __restrict__ wt,
                         __nv_bfloat16* __restrict__ xs) {
    int idx = blockIdx.x * 256 + threadIdx.x;
    if (idx >= PREP_TOT) return;
    float w;
    __nv_bfloat16* dst;
    if (idx < WT_TOT) {
        const float* W;
        int K, N, base, local;
        if (idx < 16384)       { W = Wd1; K = 64;  N = 256;  base = WT_D1; local = idx; }
        else if (idx < 81920)  { W = Wd2; K = 256; N = 256;  base = WT_D2; local = idx - 16384; }
        else if (idx < 98304)  { W = Wdo; K = 256; N = 64;   base = WT_DO; local = idx - 81920; }
        else if (idx < 114688) { W = Wo1; K = 64;  N = 256;  base = WT_O1; local = idx - 98304; }
        else if (idx < 180224) { W = Wo2; K = 256; N = 256;  base = WT_O2; local = idx - 114688; }
        else                   { W = Woo; K = 256; N = 2016; base = WT_OO; local = idx - 180224; }
        int k = local / N, n = local % N;
        w = W[(size_t)k * N + n];
        dst = wt + (size_t)2 * base + (size_t)n * 2 * K + (k >> 5) * 64 + (k & 31);
    } else {
        int e = idx - WT_TOT;
        int m = e >> 6, k = e & 63;
        w = x[(size_t)m * NDIM + k];
        dst = xs + (size_t)m * 128 + (k >> 5) * 64 + (k & 31);
    }
    __nv_bfloat16 hb = __float2bfloat16_rn(w);
    dst[0]  = hb;
    dst[32] = __float2bfloat16_rn(w - __bfloat162float(hb));
}

// ---------------------------------------------------------------------------
// bf16x3 cp.async GEMM: C[M,N] = epi(A[M,K] @ W[K,N] + bias).
// A and B both pre-split bf16 in gmem (chunked [row][k/32][hi32|lo32]).
// BM=128, BN=128, BK=32; 512 threads = 16 warps (4Mx4N), warp tile 32x32.
// 4-stage cp.async pipeline (wait_group(2)), one barrier per chunk.
// EPI_TANH writes the same split-chunk layout (feeds the next GEMM);
// EPI_BIAS/EPI_DIAG write fp32.
//
// smem: 4 stages x (A 16KB | B 16KB) = 128KB; epilogue staging
// [128][132] fp32 (67.6KB) overlays the stages.
// ---------------------------------------------------------------------------
#define STAGEB 32768
#define SOFF_B 16384
#define LDP 132
#define GEMM_SMEM (4 * STAGEB)
#define NTHR 512

template <int EPI>
__global__ void __launch_bounds__(NTHR, 1)
gemm_mma(const __nv_bfloat16* __restrict__ A4, const __nv_bfloat16* __restrict__ B4,
         const float* __restrict__ bias, char* __restrict__ C,
         int K, int N, int ldc,
         const float* __restrict__ xin, const float* __restrict__ dmin) {
    extern __shared__ char smem[];
    const uint32_t sbase = smem_u32(smem);
    const int tid = threadIdx.x;
    const int wid = tid >> 5, lane = tid & 31;
    const int g = lane >> 2, tig = lane & 3;
    const int warpM = (wid >> 2) * 32;
    const int warpN = (wid & 3) * 32;
    const int m0 = blockIdx.y * 128;
    const int n0 = blockIdx.x * 128;
    const size_t K4 = (size_t)K * 4;  // byte row stride of split operands

    // ldmatrix lane constants (validated R10).
    const uint32_t xorv = lane & 7;
    const int aRow = (lane & 7) + ((lane >> 3) & 1) * 8;
    const int aKq  = lane >> 4;
    const int bRow = (lane & 7) + ((lane >> 4) & 1) * 8;
    const int bKq  = (lane >> 3) & 1;

    float d[2][4][4];
#pragma unroll
    for (int mt = 0; mt < 2; mt++)
#pragma unroll
        for (int nt = 0; nt < 4; nt++)
#pragma unroll
            for (int j = 0; j < 4; j++) d[mt][nt][j] = 0.f;

    // Per-stage copies: 1024 A + 1024 B 16B cp.async across 512 threads.
    auto issue = [&](int t) {
        const int buf = (t & 3) * STAGEB;
#pragma unroll
        for (int i = 0; i < 2; i++) {
            int idx = tid + i * NTHR;
            int row = idx >> 3, sub = idx & 7;
            uint32_t dsw = (uint32_t)row * 128 + (((uint32_t)sub ^ (row & 7)) << 4);
            const char* sa = (const char*)A4 + (size_t)(m0 + row) * K4 +
                             (size_t)t * 128 + sub * 16;
            CP16(sbase + buf + dsw, sa);
            const char* sb = (const char*)B4 + (size_t)(n0 + row) * K4 +
                             (size_t)t * 128 + sub * 16;
            uint32_t sz = (n0 + row < N) ? 16u : 0u;  // sz=0 -> zero-fill dst
            CP16Z(sbase + buf + SOFF_B + dsw, sb, sz);
        }
    };

    auto mma_chunk = [&](int b) {
        const uint32_t Ab = sbase + b * STAGEB;
        const uint32_t Bb = Ab + SOFF_B;
#pragma unroll
        for (int ks = 0; ks < 2; ks++) {  // 2 x k16 per 32-k chunk
            const uint32_t ach = (((uint32_t)(ks * 2 + aKq)) ^ xorv) << 4;
            const uint32_t acl = (((uint32_t)(4 + ks * 2 + aKq)) ^ xorv) << 4;
            const uint32_t bch = (((uint32_t)(ks * 2 + bKq)) ^ xorv) << 4;
            const uint32_t bcl = (((uint32_t)(4 + ks * 2 + bKq)) ^ xorv) << 4;
            uint32_t ah[2][4], al[2][4];
#pragma unroll
            for (int mt = 0; mt < 2; mt++) {
                uint32_t ro = (uint32_t)(warpM + mt * 16 + aRow) * 128;
                ldsm4(ah[mt], Ab + ro + ach);
                ldsm4(al[mt], Ab + ro + acl);
            }
#pragma unroll
            for (int p = 0; p < 2; p++) {
                uint32_t bh[4], bl[4];
                uint32_t ro = (uint32_t)(warpN + p * 16 + bRow) * 128;
                ldsm4(bh, Bb + ro + bch);
                ldsm4(bl, Bb + ro + bcl);
#pragma unroll
                for (int q = 0; q < 2; q++) {
                    const int nt = p * 2 + q;
#pragma unroll
                    for (int mt = 0; mt < 2; mt++) {
                        mma16(d[mt][nt], ah[mt], bh + q * 2);  // hi*hi
                        mma16(d[mt][nt], al[mt], bh + q * 2);  // lo*hi
                        mma16(d[mt][nt], ah[mt], bl + q * 2);  // hi*lo
                    }
                }
            }
        }
    };

    const int nT = K >> 5;
#pragma unroll
    for (int s = 0; s < 3; s++) {        // prologue: stages 0..2
        if (s < nT) issue(s);
        CP_COMMIT();
    }
    for (int t = 0; t < nT; t++) {
        CP_WAIT2();                      // stage t landed
        __syncthreads();                 // visible to all; prior reads done
        if (t + 3 < nT) issue(t + 3);    // refill buffer (t-1)&3
        CP_COMMIT();
        mma_chunk(t & 3);
    }
    __syncthreads();

    // Epilogue: stage D tile in smem (overlays stages), then store.
    float* stg = reinterpret_cast<float*>(smem);  // [128][LDP]
#pragma unroll
    for (int mt = 0; mt < 2; mt++)
#pragma unroll
        for (int nt = 0; nt < 4; nt++) {
            int r = warpM + mt * 16 + g;
            int c = warpN + nt * 8 + tig * 2;
            stg[r * LDP + c]           = d[mt][nt][0];
            stg[r * LDP + c + 1]       = d[mt][nt][1];
            stg[(r + 8) * LDP + c]     = d[mt][nt][2];
            stg[(r + 8) * LDP + c + 1] = d[mt][nt][3];
        }
    __syncthreads();

    if (EPI == EPI_TANH) {
        // Thread -> (row r, 32-col group). Write hi/lo split-chunk layout:
        // per row, per chunk: [hi 32 bf16 (64B) | lo 32 bf16 (64B)].
        const int r   = tid >> 2;
        const int grp = tid & 3;
        const int gn  = n0 + grp * 32;  // global n base (chunk-aligned)
        char* rowp = C + (size_t)(m0 + r) * ((size_t)ldc * 4) +
                     ((size_t)(gn >> 5)) * 128;
#pragma unroll
        for (int j = 0; j < 4; j++) {   // 8 elems per iteration
            const float* s = stg + r * LDP + grp * 32 + j * 8;
            const float* bb = bias + gn + j * 8;
            float v[8], rf[8];
#pragma unroll
            for (int q = 0; q < 8; q++) {
                v[q] = tanhf(s[q] + bb[q]);
                rf[q] = v[q] - __bfloat162float(__float2bfloat16_rn(v[q]));
            }
            uint4 hv = make_uint4(bf16x2_rn(v[0], v[1]), bf16x2_rn(v[2], v[3]),
                                  bf16x2_rn(v[4], v[5]), bf16x2_rn(v[6], v[7]));
            uint4 lv = make_uint4(bf16x2_rn(rf[0], rf[1]), bf16x2_rn(rf[2], rf[3]),
                                  bf16x2_rn(rf[4], rf[5]), bf16x2_rn(rf[6], rf[7]));
            *reinterpret_cast<uint4*>(rowp + j * 16)      = hv;
            *reinterpret_cast<uint4*>(rowp + 64 + j * 16) = lv;
        }
    } else {
        float* Cf = reinterpret_cast<float*>(C);
        const int r  = tid >> 2;
        const int cb = (tid & 3) * 32;
#pragma unroll
        for (int j = 0; j < 8; j++) {
            int c = cb + j * 4;
            if (n0 + c < N) {  // N, c multiples of 4 -> whole float4 valid
                const float* s = stg + r * LDP + c;
                float v[4] = {s[0], s[1], s[2], s[3]};
#pragma unroll
                for (int q = 0; q < 4; q++) {
                    float val = v[q] + bias[n0 + c + q];
                    if (EPI == EPI_DIAG) {
                        float dd = fmaxf(val, 0.f) + dmin[n0 + c + q];
                        val = dd * xin[(size_t)(m0 + r) * NDIM + n0 + c + q];
                    }
                    v[q] = val;
                }
                *reinterpret_cast<float4*>(Cf + (size_t)(m0 + r) * ldc + n0 + c) =
                    make_float4(v[0], v[1], v[2], v[3]);
            }
        }
    }
}

// ---------------------------------------------------------------------------
// Final: out = L (L^T x) per batch row; L from (off, diag).
// ---------------------------------------------------------------------------
__global__ void __launch_bounds__(256)
final_kernel(const float* __restrict__ off, const float* __restrict__ diag,
             const float* __restrict__ x, float* __restrict__ out) {
    __shared__ float soff[4][OFFDIM];
    __shared__ float sx[4][NDIM];
    __shared__ float sd[4][NDIM];
    __shared__ float sv[4][NDIM];

    const int r    = threadIdx.x >> 6;
    const int lane = threadIdx.x & 63;
    const size_t row = (size_t)blockIdx.x * 4 + r;

    sx[r][lane] = x[row * NDIM + lane];
    sd[r][lane] = diag[row * NDIM + lane];
    const float* offr = off + row * OFFDIM;
    for (int i = lane; i < OFFDIM; i += 64) soff[r][i] = offr[i];
    __syncthreads();

    float v = sd[r][lane] * sx[r][lane];
    for (int i = lane + 1; i < NDIM; i++)
        v += soff[r][i * (i - 1) / 2 + lane] * sx[r][i];
    sv[r][lane] = v;
    __syncthreads();

    float o = sd[r][lane] * v;
    const int base = lane * (lane - 1) / 2;
    for (int j = 0; j < lane; j++) o += soff[r][base + j] * sv[r][j];
    out[row * NDIM + lane] = o;
}

// ---------------------------------------------------------------------------
// Launch. Inputs: x, Wd1, bd1, Wd2, bd2, Wdo, bdo, Wo1, bo1, Wo2, bo2,
//                 Woo, boo, damp_min
// Launch order keeps the Woo GEMM 6th so ncu (-s 5 -c 1) profiles it.
// ---------------------------------------------------------------------------
extern "C" void kernel_launch(void* const* d_in, const int* in_sizes, int n_in,
                              void* d_out, int out_size) {
    const float* x    = (const float*)d_in[0];
    const float* Wd1  = (const float*)d_in[1];
    const float* bd1  = (const float*)d_in[2];
    const float* Wd2  = (const float*)d_in[3];
    const float* bd2  = (const float*)d_in[4];
    const float* Wdo  = (const float*)d_in[5];
    const float* bdo  = (const float*)d_in[6];
    const float* Wo1  = (const float*)d_in[7];
    const float* bo1  = (const float*)d_in[8];
    const float* Wo2  = (const float*)d_in[9];
    const float* bo2  = (const float*)d_in[10];
    const float* Woo  = (const float*)d_in[11];
    const float* boo  = (const float*)d_in[12];
    const float* dmin = (const float*)d_in[13];
    float* out = (float*)d_out;

    float *h1, *h2, *h3, *dg, *off;
    __nv_bfloat16 *wt, *xs;
    cudaGetSymbolAddress((void**)&h1,  g_h1);
    cudaGetSymbolAddress((void**)&h2,  g_h2);
    cudaGetSymbolAddress((void**)&h3,  g_h3);
    cudaGetSymbolAddress((void**)&dg,  g_diag);
    cudaGetSymbolAddress((void**)&off, g_off);
    cudaGetSymbolAddress((void**)&wt,  g_wt);
    cudaGetSymbolAddress((void**)&xs,  g_xs);

    cudaFuncSetAttribute(gemm_mma<EPI_TANH>,
                         cudaFuncAttributeMaxDynamicSharedMemorySize, GEMM_SMEM);
    cudaFuncSetAttribute(gemm_mma<EPI_BIAS>,
                         cudaFuncAttributeMaxDynamicSharedMemorySize, GEMM_SMEM);
    cudaFuncSetAttribute(gemm_mma<EPI_DIAG>,
                         cudaFuncAttributeMaxDynamicSharedMemorySize, GEMM_SMEM);

    // 1: prep (weights + x split), single launch
    prep_all<<<(PREP_TOT + 255) / 256, 256>>>(x, Wd1, Wd2, Wdo, Wo1, Wo2, Woo,
                                              wt, xs);

    const int MB = B_ROWS / 128;  // 256 m-tiles
    // 2-3: diag hidden layers
    gemm_mma<EPI_TANH><<<dim3(2, MB), NTHR, GEMM_SMEM>>>(
        xs, wt + 2 * WT_D1, bd1, (char*)h1, NDIM, HDIM, HDIM, nullptr, nullptr);
    gemm_mma<EPI_TANH><<<dim3(2, MB), NTHR, GEMM_SMEM>>>(
        (const __nv_bfloat16*)h1, wt + 2 * WT_D2, bd2, (char*)h2, HDIM, HDIM,
        HDIM, nullptr, nullptr);
    // 4-5: off hidden layers (h1 reused after consumed by 3)
    gemm_mma<EPI_TANH><<<dim3(2, MB), NTHR, GEMM_SMEM>>>(
        xs, wt + 2 * WT_O1, bo1, (char*)h1, NDIM, HDIM, HDIM, nullptr, nullptr);
    gemm_mma<EPI_TANH><<<dim3(2, MB), NTHR, GEMM_SMEM>>>(
        (const __nv_bfloat16*)h1, wt + 2 * WT_O2, bo2, (char*)h3, HDIM, HDIM,
        HDIM, nullptr, nullptr);
    // 6: dominant Woo GEMM (profiled by ncu)
    gemm_mma<EPI_BIAS><<<dim3(16, MB), NTHR, GEMM_SMEM>>>(
        (const __nv_bfloat16*)h3, wt + 2 * WT_OO, boo, (char*)off, HDIM, OFFDIM,
        OFFDIM, nullptr, nullptr);
    // 7: diag output
    gemm_mma<EPI_DIAG><<<dim3(1, MB), NTHR, GEMM_SMEM>>>(
        (const __nv_bfloat16*)h2, wt + 2 * WT_DO, bdo, (char*)dg, HDIM, NDIM,
        NDIM, x, dmin);
    // 8: L (L^T x)
    final_kernel<<<B_ROWS / 4, 256>>>(off, dg, x, out);
}

// round 13
// speedup vs baseline: 1.8073x; 1.2213x over previous
#include <cuda_runtime.h>
#include <cuda_bf16.h>
#include <cstdint>
#include <cstddef>

// Problem constants (fixed by the reference).
#define B_ROWS 32768
#define NDIM   64
#define HDIM   256
#define OFFDIM 2016   // 64*63/2

// ---------------------------------------------------------------------------
// Device scratch. Activations h1/h2/h3 hold bf16 hi/lo split pairs
// (layout [M][K/32][hi 32 bf16 | lo 32 bf16] = 4 bytes/elem, same as fp32).
// ---------------------------------------------------------------------------
__device__ float g_h1[(size_t)B_ROWS * HDIM];
__device__ float g_h2[(size_t)B_ROWS * HDIM];
__device__ float g_h3[(size_t)B_ROWS * HDIM];
__device__ float g_diag[(size_t)B_ROWS * NDIM];
__device__ float g_off[(size_t)B_ROWS * OFFDIM];
__device__ __nv_bfloat16 g_xs[(size_t)B_ROWS * 2 * NDIM];  // x pre-split

// Transposed + bf16-split weights, chunked: per n-row, per 32-k group:
// [hi 32 | lo 32] bf16. Offsets in "elements" (1 elem = hi+lo pair = 4B).
#define WT_D1 0
#define WT_D2 16384
#define WT_DO 81920
#define WT_O1 98304
#define WT_O2 114688
#define WT_OO 180224
#define WT_TOT 696320
__device__ __nv_bfloat16 g_wt[(size_t)2 * WT_TOT];

// ---------------------------------------------------------------------------
// Helpers
// ---------------------------------------------------------------------------
__device__ __forceinline__ uint32_t bf16x2_rn(float klo, float khi) {
    uint32_t r;  // low half <- klo (lower index), high half <- khi
    asm("cvt.rn.bf16x2.f32 %0, %1, %2;" : "=r"(r) : "f"(khi), "f"(klo));
    return r;
}
__device__ __forceinline__ void mma16(float* d, const uint32_t* a,
                                      const uint32_t* b) {
    asm volatile(
        "mma.sync.aligned.m16n8k16.row.col.f32.bf16.bf16.f32 "
        "{%0,%1,%2,%3}, {%4,%5,%6,%7}, {%8,%9}, {%0,%1,%2,%3};"
        : "+f"(d[0]), "+f"(d[1]), "+f"(d[2]), "+f"(d[3])
        : "r"(a[0]), "r"(a[1]), "r"(a[2]), "r"(a[3]), "r"(b[0]), "r"(b[1]));
}
__device__ __forceinline__ void ldsm4(uint32_t* r, uint32_t addr) {
    asm volatile(
        "ldmatrix.sync.aligned.m8n8.x4.shared.b16 {%0,%1,%2,%3}, [%4];"
        : "=r"(r[0]), "=r"(r[1]), "=r"(r[2]), "=r"(r[3]) : "r"(addr));
}
__device__ __forceinline__ uint32_t smem_u32(const void* p) {
    uint32_t a;
    asm("{ .reg .u64 t; cvta.to.shared.u64 t, %1; cvt.u32.u64 %0, t; }"
        : "=r"(a) : "l"(p));
    return a;
}
#define CP16(d, s) \
    asm volatile("cp.async.cg.shared.global [%0], [%1], 16;" \
                 :: "r"(d), "l"(s))
#define CP16Z(d, s, sz) \
    asm volatile("cp.async.cg.shared.global [%0], [%1], 16, %2;" \
                 :: "r"(d), "l"(s), "r"(sz))
#define CP_COMMIT() asm volatile("cp.async.commit_group;" ::: "memory")
#define CP_WAIT2()  asm volatile("cp.async.wait_group 2;" ::: "memory")

enum { EPI_TANH = 0, EPI_BIAS = 1, EPI_DIAG = 2 };

// ---------------------------------------------------------------------------
// Prep: weights W[K,N] fp32 -> split-chunked Wt[n][k-chunks]; x -> g_xs.
// ---------------------------------------------------------------------------
#define PREP_TOT (WT_TOT + B_ROWS * NDIM)
__global__ void prep_all(const float* __restrict__ x,
                         const float* __restrict__ Wd1, const float* __restrict__ Wd2,
                         const float* __restrict__ Wdo, const float* __restrict__ Wo1,
                         const float* __restrict__ Wo2, const float* __restrict__ Woo,
                         __nv_bfloat16* __restrict__ wt,
                         __nv_bfloat16* __restrict__ xs) {
    int idx = blockIdx.x * 256 + threadIdx.x;
    if (idx >= PREP_TOT) return;
    float w;
    __nv_bfloat16* dst;
    if (idx < WT_TOT) {
        const float* W;
        int K, N, base, local;
        if (idx < 16384)       { W = Wd1; K = 64;  N = 256;  base = WT_D1; local = idx; }
        else if (idx < 81920)  { W = Wd2; K = 256; N = 256;  base = WT_D2; local = idx - 16384; }
        else if (idx < 98304)  { W = Wdo; K = 256; N = 64;   base = WT_DO; local = idx - 81920; }
        else if (idx < 114688) { W = Wo1; K = 64;  N = 256;  base = WT_O1; local = idx - 98304; }
        else if (idx < 180224) { W = Wo2; K = 256; N = 256;  base = WT_O2; local = idx - 114688; }
        else                   { W = Woo; K = 256; N = 2016; base = WT_OO; local = idx - 180224; }
        int k = local / N, n = local % N;
        w = W[(size_t)k * N + n];
        dst = wt + (size_t)2 * base + (size_t)n * 2 * K + (k >> 5) * 64 + (k & 31);
    } else {
        int e = idx - WT_TOT;
        int m = e >> 6, k = e & 63;
        w = x[(size_t)m * NDIM + k];
        dst = xs + (size_t)m * 128 + (k >> 5) * 64 + (k & 31);
    }
    __nv_bfloat16 hb = __float2bfloat16_rn(w);
    dst[0]  = hb;
    dst[32] = __float2bfloat16_rn(w - __bfloat162float(hb));
}

// ---------------------------------------------------------------------------
// bf16x3 cp.async GEMM: C[M,N] = epi(A[M,K] @ W[K,N] + bias).
// BM=256, BN=128, BK=32; 256 threads = 8 warps (4Mx2N), warp tile 64x64:
// halves ldsm fragment wavefronts per MAC vs the R12 32x32 warp tile
// (the measured limiter). 4-stage cp.async pipeline, wait_group(2).
//
// smem: 4 stages x (A 32KB | B 16KB) = 192KB; epilogue staging
// [256][132] fp32 (135KB) overlays the stages.
// ---------------------------------------------------------------------------
#define BM 256
#define BN 128
#define STAGEB 49152
#define SOFF_B 32768
#define LDP 132
#define GEMM_SMEM (4 * STAGEB)
#define NTHR 256

template <int EPI>
__global__ void __launch_bounds__(NTHR, 1)
gemm_mma(const __nv_bfloat16* __restrict__ A4, const __nv_bfloat16* __restrict__ B4,
         const float* __restrict__ bias, char* __restrict__ C,
         int K, int N, int ldc,
         const float* __restrict__ xin, const float* __restrict__ dmin) {
    extern __shared__ char smem[];
    const uint32_t sbase = smem_u32(smem);
    const int tid = threadIdx.x;
    const int wid = tid >> 5, lane = tid & 31;
    const int g = lane >> 2, tig = lane & 3;
    const int warpM = (wid >> 1) * 64;   // 4 M rows of warps
    const int warpN = (wid & 1) * 64;    // 2 N cols of warps
    const int m0 = blockIdx.y * BM;
    const int n0 = blockIdx.x * BN;
    const size_t K4 = (size_t)K * 4;     // byte row stride of split operands

    // ldmatrix lane constants (validated R10/R12).
    const uint32_t xorv = lane & 7;
    const int aRow = (lane & 7) + ((lane >> 3) & 1) * 8;
    const int aKq  = lane >> 4;
    const int bRow = (lane & 7) + ((lane >> 4) & 1) * 8;
    const int bKq  = (lane >> 3) & 1;

    float d[4][8][4];
#pragma unroll
    for (int mt = 0; mt < 4; mt++)
#pragma unroll
        for (int nt = 0; nt < 8; nt++)
#pragma unroll
            for (int j = 0; j < 4; j++) d[mt][nt][j] = 0.f;

    // Per stage: A 2048 + B 1024 x 16B cp.async over 256 threads (12/thread).
    auto issue = [&](int t) {
        const int buf = (t & 3) * STAGEB;
#pragma unroll
        for (int i = 0; i < 8; i++) {      // A: rows 0..255
            int idx = tid + i * NTHR;
            int row = idx >> 3, sub = idx & 7;
            uint32_t dsw = (uint32_t)row * 128 + (((uint32_t)sub ^ (row & 7)) << 4);
            const char* sa = (const char*)A4 + (size_t)(m0 + row) * K4 +
                             (size_t)t * 128 + sub * 16;
            CP16(sbase + buf + dsw, sa);
        }
#pragma unroll
        for (int i = 0; i < 4; i++) {      // B: rows 0..127
            int idx = tid + i * NTHR;
            int row = idx >> 3, sub = idx & 7;
            uint32_t dsw = (uint32_t)row * 128 + (((uint32_t)sub ^ (row & 7)) << 4);
            const char* sb = (const char*)B4 + (size_t)(n0 + row) * K4 +
                             (size_t)t * 128 + sub * 16;
            uint32_t sz = (n0 + row < N) ? 16u : 0u;  // sz=0 -> zero-fill
            CP16Z(sbase + buf + SOFF_B + dsw, sb, sz);
        }
    };

    auto mma_chunk = [&](int b) {
        const uint32_t Ab = sbase + b * STAGEB;
        const uint32_t Bb = Ab + SOFF_B;
#pragma unroll
        for (int ks = 0; ks < 2; ks++) {  // 2 x k16 per 32-k chunk
            const uint32_t ach = (((uint32_t)(ks * 2 + aKq)) ^ xorv) << 4;
            const uint32_t acl = (((uint32_t)(4 + ks * 2 + aKq)) ^ xorv) << 4;
            const uint32_t bch = (((uint32_t)(ks * 2 + bKq)) ^ xorv) << 4;
            const uint32_t bcl = (((uint32_t)(4 + ks * 2 + bKq)) ^ xorv) << 4;
            uint32_t ah[4][4], al[4][4];
#pragma unroll
            for (int mt = 0; mt < 4; mt++) {
                uint32_t ro = (uint32_t)(warpM + mt * 16 + aRow) * 128;
                ldsm4(ah[mt], Ab + ro + ach);
                ldsm4(al[mt], Ab + ro + acl);
            }
#pragma unroll
            for (int p = 0; p < 4; p++) {  // 4 n16-tiles (Nw=64)
                uint32_t bh[4], bl[4];
                uint32_t ro = (uint32_t)(warpN + p * 16 + bRow) * 128;
                ldsm4(bh, Bb + ro + bch);
                ldsm4(bl, Bb + ro + bcl);
#pragma unroll
                for (int q = 0; q < 2; q++) {
                    const int nt = p * 2 + q;
#pragma unroll
                    for (int mt = 0; mt < 4; mt++) {
                        mma16(d[mt][nt], ah[mt], bh + q * 2);  // hi*hi
                        mma16(d[mt][nt], al[mt], bh + q * 2);  // lo*hi
                        mma16(d[mt][nt], ah[mt], bl + q * 2);  // hi*lo
                    }
                }
            }
        }
    };

    const int nT = K >> 5;
#pragma unroll
    for (int s = 0; s < 3; s++) {        // prologue: stages 0..2
        if (s < nT) issue(s);
        CP_COMMIT();
    }
    for (int t = 0; t < nT; t++) {
        CP_WAIT2();                      // stage t landed
        __syncthreads();                 // visible to all; prior reads done
        if (t + 3 < nT) issue(t + 3);
        CP_COMMIT();
        mma_chunk(t & 3);
    }
    __syncthreads();

    // Epilogue: stage D tile [256][LDP] in smem (overlays stages).
    float* stg = reinterpret_cast<float*>(smem);
#pragma unroll
    for (int mt = 0; mt < 4; mt++)
#pragma unroll
        for (int nt = 0; nt < 8; nt++) {
            int r = warpM + mt * 16 + g;
            int c = warpN + nt * 8 + tig * 2;
            stg[r * LDP + c]           = d[mt][nt][0];
            stg[r * LDP + c + 1]       = d[mt][nt][1];
            stg[(r + 8) * LDP + c]     = d[mt][nt][2];
            stg[(r + 8) * LDP + c + 1] = d[mt][nt][3];
        }
    __syncthreads();

    // Warp-per-row stores: each warp handles 32 rows, lane l covers 16B of
    // the row's 512B output region -> fully coalesced.
    if (EPI == EPI_TANH) {
        // Split-chunk layout per row: 4 chunks x [hi 32 bf16 | lo 32 bf16].
        const int c = lane >> 3;          // chunk 0..3
        const int h = (lane >> 2) & 1;    // 0=hi half, 1=lo half
        const int s = lane & 3;           // 16B slot within half
        const int eb = c * 32 + s * 8;    // first of 8 elems this lane packs
#pragma unroll 1
        for (int rr = 0; rr < 32; rr++) {
            const int row = wid + rr * 8;
            const float* sp = stg + row * LDP + eb;
            const float* bb = bias + n0 + eb;
            float v[8];
#pragma unroll
            for (int q = 0; q < 8; q++) v[q] = tanhf(sp[q] + bb[q]);
            uint4 pk;
            if (h == 0) {
                pk = make_uint4(bf16x2_rn(v[0], v[1]), bf16x2_rn(v[2], v[3]),
                                bf16x2_rn(v[4], v[5]), bf16x2_rn(v[6], v[7]));
            } else {
                float rf[8];
#pragma unroll
                for (int q = 0; q < 8; q++)
                    rf[q] = v[q] - __bfloat162float(__float2bfloat16_rn(v[q]));
                pk = make_uint4(bf16x2_rn(rf[0], rf[1]), bf16x2_rn(rf[2], rf[3]),
                                bf16x2_rn(rf[4], rf[5]), bf16x2_rn(rf[6], rf[7]));
            }
            char* rowp = C + (size_t)(m0 + row) * ((size_t)ldc * 4) +
                         ((size_t)(n0 >> 5)) * 128;
            *reinterpret_cast<uint4*>(rowp + c * 128 + h * 64 + s * 16) = pk;
        }
    } else {
        float* Cf = reinterpret_cast<float*>(C);
        const int col = lane * 4;
#pragma unroll 1
        for (int rr = 0; rr < 32; rr++) {
            const int row = wid + rr * 8;
            if (n0 + col < N) {  // N, col multiples of 4 -> whole float4 ok
                const float* sp = stg + row * LDP + col;
                float v[4] = {sp[0], sp[1], sp[2], sp[3]};
#pragma unroll
                for (int q = 0; q < 4; q++) {
                    float val = v[q] + bias[n0 + col + q];
                    if (EPI == EPI_DIAG) {
                        float dd = fmaxf(val, 0.f) + dmin[n0 + col + q];
                        val = dd * xin[(size_t)(m0 + row) * NDIM + n0 + col + q];
                    }
                    v[q] = val;
                }
                *reinterpret_cast<float4*>(Cf + (size_t)(m0 + row) * ldc + n0 + col) =
                    make_float4(v[0], v[1], v[2], v[3]);
            }
        }
    }
}

// ---------------------------------------------------------------------------
// Final: out = L (L^T x) per batch row; L from (off, diag).
// ---------------------------------------------------------------------------
__global__ void __launch_bounds__(256)
final_kernel(const float* __restrict__ off, const float* __restrict__ diag,
             const float* __restrict__ x, float* __restrict__ out) {
    __shared__ float soff[4][OFFDIM];
    __shared__ float sx[4][NDIM];
    __shared__ float sd[4][NDIM];
    __shared__ float sv[4][NDIM];

    const int r    = threadIdx.x >> 6;
    const int lane = threadIdx.x & 63;
    const size_t row = (size_t)blockIdx.x * 4 + r;

    sx[r][lane] = x[row * NDIM + lane];
    sd[r][lane] = diag[row * NDIM + lane];
    const float* offr = off + row * OFFDIM;
    for (int i = lane; i < OFFDIM; i += 64) soff[r][i] = offr[i];
    __syncthreads();

    float v = sd[r][lane] * sx[r][lane];
    for (int i = lane + 1; i < NDIM; i++)
        v += soff[r][i * (i - 1) / 2 + lane] * sx[r][i];
    sv[r][lane] = v;
    __syncthreads();

    float o = sd[r][lane] * v;
    const int base = lane * (lane - 1) / 2;
    for (int j = 0; j < lane; j++) o += soff[r][base + j] * sv[r][j];
    out[row * NDIM + lane] = o;
}

// ---------------------------------------------------------------------------
// Launch. Inputs: x, Wd1, bd1, Wd2, bd2, Wdo, bdo, Wo1, bo1, Wo2, bo2,
//                 Woo, boo, damp_min
// Launch order keeps the Woo GEMM 6th so ncu (-s 5 -c 1) profiles it.
// ---------------------------------------------------------------------------
extern "C" void kernel_launch(void* const* d_in, const int* in_sizes, int n_in,
                              void* d_out, int out_size) {
    const float* x    = (const float*)d_in[0];
    const float* Wd1  = (const float*)d_in[1];
    const float* bd1  = (const float*)d_in[2];
    const float* Wd2  = (const float*)d_in[3];
    const float* bd2  = (const float*)d_in[4];
    const float* Wdo  = (const float*)d_in[5];
    const float* bdo  = (const float*)d_in[6];
    const float* Wo1  = (const float*)d_in[7];
    const float* bo1  = (const float*)d_in[8];
    const float* Wo2  = (const float*)d_in[9];
    const float* bo2  = (const float*)d_in[10];
    const float* Woo  = (const float*)d_in[11];
    const float* boo  = (const float*)d_in[12];
    const float* dmin = (const float*)d_in[13];
    float* out = (float*)d_out;

    float *h1, *h2, *h3, *dg, *off;
    __nv_bfloat16 *wt, *xs;
    cudaGetSymbolAddress((void**)&h1,  g_h1);
    cudaGetSymbolAddress((void**)&h2,  g_h2);
    cudaGetSymbolAddress((void**)&h3,  g_h3);
    cudaGetSymbolAddress((void**)&dg,  g_diag);
    cudaGetSymbolAddress((void**)&off, g_off);
    cudaGetSymbolAddress((void**)&wt,  g_wt);
    cudaGetSymbolAddress((void**)&xs,  g_xs);

    cudaFuncSetAttribute(gemm_mma<EPI_TANH>,
                         cudaFuncAttributeMaxDynamicSharedMemorySize, GEMM_SMEM);
    cudaFuncSetAttribute(gemm_mma<EPI_BIAS>,
                         cudaFuncAttributeMaxDynamicSharedMemorySize, GEMM_SMEM);
    cudaFuncSetAttribute(gemm_mma<EPI_DIAG>,
                         cudaFuncAttributeMaxDynamicSharedMemorySize, GEMM_SMEM);

    // 1: prep (weights + x split), single launch
    prep_all<<<(PREP_TOT + 255) / 256, 256>>>(x, Wd1, Wd2, Wdo, Wo1, Wo2, Woo,
                                              wt, xs);

    const int MB = B_ROWS / BM;  // 128 m-tiles
    // 2-3: diag hidden layers
    gemm_mma<EPI_TANH><<<dim3(2, MB), NTHR, GEMM_SMEM>>>(
        xs, wt + 2 * WT_D1, bd1, (char*)h1, NDIM, HDIM, HDIM, nullptr, nullptr);
    gemm_mma<EPI_TANH><<<dim3(2, MB), NTHR, GEMM_SMEM>>>(
        (const __nv_bfloat16*)h1, wt + 2 * WT_D2, bd2, (char*)h2, HDIM, HDIM,
        HDIM, nullptr, nullptr);
    // 4-5: off hidden layers (h1 reused after consumed by 3)
    gemm_mma<EPI_TANH><<<dim3(2, MB), NTHR, GEMM_SMEM>>>(
        xs, wt + 2 * WT_O1, bo1, (char*)h1, NDIM, HDIM, HDIM, nullptr, nullptr);
    gemm_mma<EPI_TANH><<<dim3(2, MB), NTHR, GEMM_SMEM>>>(
        (const __nv_bfloat16*)h1, wt + 2 * WT_O2, bo2, (char*)h3, HDIM, HDIM,
        HDIM, nullptr, nullptr);
    // 6: dominant Woo GEMM (profiled by ncu)
    gemm_mma<EPI_BIAS><<<dim3(16, MB), NTHR, GEMM_SMEM>>>(
        (const __nv_bfloat16*)h3, wt + 2 * WT_OO, boo, (char*)off, HDIM, OFFDIM,
        OFFDIM, nullptr, nullptr);
    // 7: diag output
    gemm_mma<EPI_DIAG><<<dim3(1, MB), NTHR, GEMM_SMEM>>>(
        (const __nv_bfloat16*)h2, wt + 2 * WT_DO, bdo, (char*)dg, HDIM, NDIM,
        NDIM, x, dmin);
    // 8: L (L^T x)
    final_kernel<<<B_ROWS / 4, 256>>>(off, dg, x, out);
}

// round 14
// speedup vs baseline: 1.8204x; 1.0073x over previous
#include <cuda_runtime.h>
#include <cuda_bf16.h>
#include <cstdint>
#include <cstddef>

// Problem constants (fixed by the reference).
#define B_ROWS 32768
#define NDIM   64
#define HDIM   256
#define OFFDIM 2016   // 64*63/2

// ---------------------------------------------------------------------------
// Device scratch. h1 holds BOTH layer-1 outputs (d | o) as bf16 hi/lo split
// pairs: [M][16 chunks x 128B] (chunks 0-7 = d-branch, 8-15 = o-branch).
// h2/h3 hold layer-2 outputs (256 elems/row, split-chunk). diag/off fp32.
// ---------------------------------------------------------------------------
__device__ float g_h1[(size_t)B_ROWS * 512];
__device__ float g_h2[(size_t)B_ROWS * HDIM];
__device__ float g_h3[(size_t)B_ROWS * HDIM];
__device__ float g_diag[(size_t)B_ROWS * NDIM];
__device__ float g_off[(size_t)B_ROWS * OFFDIM];
__device__ __nv_bfloat16 g_xs[(size_t)B_ROWS * 2 * NDIM];  // x pre-split
__device__ float g_b1[512];                                 // concat(bd1,bo1)

// Split-chunked weights: per n-row, per 32-k group [hi 32 | lo 32] bf16.
// Regions (element offsets; 1 elem = hi+lo pair = 4B):
//   L1 (Wd1|Wo1 concat, K=64, N=512), D2, O2 (K=256,N=256),
//   DO (K=256,N=64), OO (K=256,N=2016).
#define WT_L1 0
#define WT_D2 32768
#define WT_O2 98304
#define WT_DO 163840
#define WT_OO 180224
#define WT_TOT 696320
__device__ __nv_bfloat16 g_wt[(size_t)2 * WT_TOT];

// ---------------------------------------------------------------------------
// Helpers
// ---------------------------------------------------------------------------
__device__ __forceinline__ uint32_t bf16x2_rn(float klo, float khi) {
    uint32_t r;  // low half <- klo (lower index), high half <- khi
    asm("cvt.rn.bf16x2.f32 %0, %1, %2;" : "=r"(r) : "f"(khi), "f"(klo));
    return r;
}
__device__ __forceinline__ void mma16(float* d, const uint32_t* a,
                                      const uint32_t* b) {
    asm volatile(
        "mma.sync.aligned.m16n8k16.row.col.f32.bf16.bf16.f32 "
        "{%0,%1,%2,%3}, {%4,%5,%6,%7}, {%8,%9}, {%0,%1,%2,%3};"
        : "+f"(d[0]), "+f"(d[1]), "+f"(d[2]), "+f"(d[3])
        : "r"(a[0]), "r"(a[1]), "r"(a[2]), "r"(a[3]), "r"(b[0]), "r"(b[1]));
}
__device__ __forceinline__ void ldsm4(uint32_t* r, uint32_t addr) {
    asm volatile(
        "ldmatrix.sync.aligned.m8n8.x4.shared.b16 {%0,%1,%2,%3}, [%4];"
        : "=r"(r[0]), "=r"(r[1]), "=r"(r[2]), "=r"(r[3]) : "r"(addr));
}
__device__ __forceinline__ uint32_t smem_u32(const void* p) {
    uint32_t a;
    asm("{ .reg .u64 t; cvta.to.shared.u64 t, %1; cvt.u32.u64 %0, t; }"
        : "=r"(a) : "l"(p));
    return a;
}
#define CP16(d, s) \
    asm volatile("cp.async.cg.shared.global [%0], [%1], 16;" \
                 :: "r"(d), "l"(s))
#define CP16Z(d, s, sz) \
    asm volatile("cp.async.cg.shared.global [%0], [%1], 16, %2;" \
                 :: "r"(d), "l"(s), "r"(sz))
#define CP_COMMIT() asm volatile("cp.async.commit_group;" ::: "memory")
#define CP_WAIT2()  asm volatile("cp.async.wait_group 2;" ::: "memory")

enum { EPI_TANH = 0, EPI_BIAS = 1, EPI_DIAG = 2 };

// ---------------------------------------------------------------------------
// Prep 1: all weights -> split-chunked g_wt; also concat bias into g_b1.
// ---------------------------------------------------------------------------
__global__ void prep_w(const float* __restrict__ Wd1, const float* __restrict__ Wd2,
                       const float* __restrict__ Wdo, const float* __restrict__ Wo1,
                       const float* __restrict__ Wo2, const float* __restrict__ Woo,
                       const float* __restrict__ bd1, const float* __restrict__ bo1,
                       __nv_bfloat16* __restrict__ wt, float* __restrict__ b1) {
    int idx = blockIdx.x * 256 + threadIdx.x;
    if (idx < 512) b1[idx] = (idx < 256) ? bd1[idx] : bo1[idx - 256];
    if (idx >= WT_TOT) return;
    float w;
    int K, n, k, base;
    if (idx < 32768) {                       // L1: K=64, N=512
        base = WT_L1; K = 64;
        n = idx & 511; k = idx >> 9;
        w = (n < 256) ? Wd1[(size_t)k * 256 + n] : Wo1[(size_t)k * 256 + (n - 256)];
    } else if (idx < 98304) {                // D2: K=256, N=256
        base = WT_D2; K = 256;
        int local = idx - 32768;
        k = local / 256; n = local % 256;
        w = Wd2[(size_t)k * 256 + n];
    } else if (idx < 163840) {               // O2
        base = WT_O2; K = 256;
        int local = idx - 98304;
        k = local / 256; n = local % 256;
        w = Wo2[(size_t)k * 256 + n];
    } else if (idx < 180224) {               // DO: K=256, N=64
        base = WT_DO; K = 256;
        int local = idx - 163840;
        k = local / 64; n = local % 64;
        w = Wdo[(size_t)k * 64 + n];
    } else {                                 // OO: K=256, N=2016
        base = WT_OO; K = 256;
        int local = idx - 180224;
        k = local / 2016; n = local % 2016;
        w = Woo[(size_t)k * 2016 + n];
    }
    __nv_bfloat16* dst = wt + (size_t)2 * base + (size_t)n * 2 * K +
                         (k >> 5) * 64 + (k & 31);
    __nv_bfloat16 hb = __float2bfloat16_rn(w);
    dst[0]  = hb;
    dst[32] = __float2bfloat16_rn(w - __bfloat162float(hb));
}

// Prep 2: x -> split-chunked g_xs.
__global__ void prep_x(const float* __restrict__ x,
                       __nv_bfloat16* __restrict__ xs) {
    int idx = blockIdx.x * 256 + threadIdx.x;
    int m = idx >> 6, k = idx & 63;
    float w = x[(size_t)m * NDIM + k];
    __nv_bfloat16* dst = xs + (size_t)m * 128 + (k >> 5) * 64 + (k & 31);
    __nv_bfloat16 hb = __float2bfloat16_rn(w);
    dst[0]  = hb;
    dst[32] = __float2bfloat16_rn(w - __bfloat162float(hb));
}

// ---------------------------------------------------------------------------
// bf16x3 cp.async GEMM: C[M,N] = epi(A[M,K] @ W[K,N] + bias).
// BM=256, BN=128, BK=32; 256 threads = 8 warps (4Mx2N), warp tile 64x64.
// 4-stage cp.async pipeline. blockIdx.z selects operand set (0/1) to batch
// two same-shape GEMMs in one launch. lda = A row stride in 4B elements.
// Copy addressing hoisted out of the stage loop (R13 alu=16.5% fix).
// ---------------------------------------------------------------------------
#define BM 256
#define BN 128
#define STAGEB 49152
#define SOFF_B 32768
#define LDP 132
#define GEMM_SMEM (4 * STAGEB)
#define NTHR 256

template <int EPI>
__global__ void __launch_bounds__(NTHR, 1)
gemm_mma(const __nv_bfloat16* __restrict__ A0, const __nv_bfloat16* __restrict__ A1,
         const __nv_bfloat16* __restrict__ B0, const __nv_bfloat16* __restrict__ B1,
         const float* __restrict__ bias0, const float* __restrict__ bias1,
         char* __restrict__ C0, char* __restrict__ C1,
         int lda, int K, int N, int ldc,
         const float* __restrict__ xin, const float* __restrict__ dmin) {
    extern __shared__ char smem[];
    const uint32_t sbase = smem_u32(smem);
    const int tid = threadIdx.x;
    const int wid = tid >> 5, lane = tid & 31;
    const int g = lane >> 2, tig = lane & 3;
    const int warpM = (wid >> 1) * 64;
    const int warpN = (wid & 1) * 64;
    const int m0 = blockIdx.y * BM;
    const int n0 = blockIdx.x * BN;

    const __nv_bfloat16* A4 = blockIdx.z ? A1 : A0;
    const __nv_bfloat16* B4 = blockIdx.z ? B1 : B0;
    const float* bias = blockIdx.z ? bias1 : bias0;
    char* C = blockIdx.z ? C1 : C0;

    const size_t K4a = (size_t)lda * 4;  // A row stride bytes
    const size_t K4b = (size_t)K * 4;    // B row stride bytes

    // Hoisted per-thread copy addressing.
    const int row0 = tid >> 3;           // 0..31
    const int sub  = tid & 7;
    const uint32_t dsw0 = (uint32_t)row0 * 128 +
                          (((uint32_t)sub ^ (row0 & 7)) << 4);
    const char* aBase = (const char*)A4 + (size_t)(m0 + row0) * K4a + sub * 16;
    const char* bBase = (const char*)B4 + (size_t)(n0 + row0) * K4b + sub * 16;

    // ldmatrix lane constants (validated R10/R12/R13).
    const uint32_t xorv = lane & 7;
    const int aRow = (lane & 7) + ((lane >> 3) & 1) * 8;
    const int aKq  = lane >> 4;
    const int bRow = (lane & 7) + ((lane >> 4) & 1) * 8;
    const int bKq  = (lane >> 3) & 1;

    float d[4][8][4];
#pragma unroll
    for (int mt = 0; mt < 4; mt++)
#pragma unroll
        for (int nt = 0; nt < 8; nt++)
#pragma unroll
            for (int j = 0; j < 4; j++) d[mt][nt][j] = 0.f;

    auto issue = [&](int t) {
        const int buf = (t & 3) * STAGEB;
        const char* ap = aBase + (size_t)t * 128;
#pragma unroll
        for (int i = 0; i < 8; i++)          // A rows row0 + 32i
            CP16(sbase + buf + dsw0 + i * 4096, ap + (size_t)i * 32 * K4a);
        const char* bp = bBase + (size_t)t * 128;
#pragma unroll
        for (int i = 0; i < 4; i++) {        // B rows row0 + 32i
            uint32_t sz = (n0 + row0 + 32 * i < N) ? 16u : 0u;  // 0 => zero-fill
            CP16Z(sbase + buf + SOFF_B + dsw0 + i * 4096,
                  bp + (size_t)i * 32 * K4b, sz);
        }
    };

    auto mma_chunk = [&](int b) {
        const uint32_t Ab = sbase + b * STAGEB;
        const uint32_t Bb = Ab + SOFF_B;
#pragma unroll
        for (int ks = 0; ks < 2; ks++) {
            const uint32_t ach = (((uint32_t)(ks * 2 + aKq)) ^ xorv) << 4;
            const uint32_t acl = (((uint32_t)(4 + ks * 2 + aKq)) ^ xorv) << 4;
            const uint32_t bch = (((uint32_t)(ks * 2 + bKq)) ^ xorv) << 4;
            const uint32_t bcl = (((uint32_t)(4 + ks * 2 + bKq)) ^ xorv) << 4;
            uint32_t ah[4][4], al[4][4];
#pragma unroll
            for (int mt = 0; mt < 4; mt++) {
                uint32_t ro = (uint32_t)(warpM + mt * 16 + aRow) * 128;
                ldsm4(ah[mt], Ab + ro + ach);
                ldsm4(al[mt], Ab + ro + acl);
            }
#pragma unroll
            for (int p = 0; p < 4; p++) {
                uint32_t bh[4], bl[4];
                uint32_t ro = (uint32_t)(warpN + p * 16 + bRow) * 128;
                ldsm4(bh, Bb + ro + bch);
                ldsm4(bl, Bb + ro + bcl);
#pragma unroll
                for (int q = 0; q < 2; q++) {
                    const int nt = p * 2 + q;
#pragma unroll
                    for (int mt = 0; mt < 4; mt++) {
                        mma16(d[mt][nt], ah[mt], bh + q * 2);  // hi*hi
                        mma16(d[mt][nt], al[mt], bh + q * 2);  // lo*hi
                        mma16(d[mt][nt], ah[mt], bl + q * 2);  // hi*lo
                    }
                }
            }
        }
    };

    const int nT = K >> 5;
#pragma unroll
    for (int s = 0; s < 3; s++) {
        if (s < nT) issue(s);
        CP_COMMIT();
    }
    for (int t = 0; t < nT; t++) {
        CP_WAIT2();
        __syncthreads();
        if (t + 3 < nT) issue(t + 3);
        CP_COMMIT();
        mma_chunk(t & 3);
    }
    __syncthreads();

    // Epilogue: stage D tile [256][LDP] in smem (overlays stages).
    float* stg = reinterpret_cast<float*>(smem);
#pragma unroll
    for (int mt = 0; mt < 4; mt++)
#pragma unroll
        for (int nt = 0; nt < 8; nt++) {
            int r = warpM + mt * 16 + g;
            int c = warpN + nt * 8 + tig * 2;
            stg[r * LDP + c]           = d[mt][nt][0];
            stg[r * LDP + c + 1]       = d[mt][nt][1];
            stg[(r + 8) * LDP + c]     = d[mt][nt][2];
            stg[(r + 8) * LDP + c + 1] = d[mt][nt][3];
        }
    __syncthreads();

    // Warp-per-row stores: warp handles 32 rows; lane covers 16B -> coalesced.
    if (EPI == EPI_TANH) {
        // Split-chunk output: per row, 4 chunks x [hi 32 bf16 | lo 32 bf16].
        const int c = lane >> 3;
        const int h = (lane >> 2) & 1;
        const int s = lane & 3;
        const int eb = c * 32 + s * 8;
#pragma unroll 1
        for (int rr = 0; rr < 32; rr++) {
            const int row = wid + rr * 8;
            const float* sp = stg + row * LDP + eb;
            const float* bb = bias + n0 + eb;
            float v[8];
#pragma unroll
            for (int q = 0; q < 8; q++) v[q] = tanhf(sp[q] + bb[q]);
            uint4 pk;
            if (h == 0) {
                pk = make_uint4(bf16x2_rn(v[0], v[1]), bf16x2_rn(v[2], v[3]),
                                bf16x2_rn(v[4], v[5]), bf16x2_rn(v[6], v[7]));
            } else {
                float rf[8];
#pragma unroll
                for (int q = 0; q < 8; q++)
                    rf[q] = v[q] - __bfloat162float(__float2bfloat16_rn(v[q]));
                pk = make_uint4(bf16x2_rn(rf[0], rf[1]), bf16x2_rn(rf[2], rf[3]),
                                bf16x2_rn(rf[4], rf[5]), bf16x2_rn(rf[6], rf[7]));
            }
            char* rowp = C + (size_t)(m0 + row) * ((size_t)ldc * 4) +
                         ((size_t)(n0 >> 5)) * 128;
            *reinterpret_cast<uint4*>(rowp + c * 128 + h * 64 + s * 16) = pk;
        }
    } else {
        float* Cf = reinterpret_cast<float*>(C);
        const int col = lane * 4;
#pragma unroll 1
        for (int rr = 0; rr < 32; rr++) {
            const int row = wid + rr * 8;
            if (n0 + col < N) {
                const float* sp = stg + row * LDP + col;
                float v[4] = {sp[0], sp[1], sp[2], sp[3]};
#pragma unroll
                for (int q = 0; q < 4; q++) {
                    float val = v[q] + bias[n0 + col + q];
                    if (EPI == EPI_DIAG) {
                        float dd = fmaxf(val, 0.f) + dmin[n0 + col + q];
                        val = dd * xin[(size_t)(m0 + row) * NDIM + n0 + col + q];
                    }
                    v[q] = val;
                }
                *reinterpret_cast<float4*>(Cf + (size_t)(m0 + row) * ldc + n0 + col) =
                    make_float4(v[0], v[1], v[2], v[3]);
            }
        }
    }
}

// ---------------------------------------------------------------------------
// Final: out = L (L^T x) per batch row; L from (off, diag).
// ---------------------------------------------------------------------------
__global__ void __launch_bounds__(256)
final_kernel(const float* __restrict__ off, const float* __restrict__ diag,
             const float* __restrict__ x, float* __restrict__ out) {
    __shared__ float soff[4][OFFDIM];
    __shared__ float sx[4][NDIM];
    __shared__ float sd[4][NDIM];
    __shared__ float sv[4][NDIM];

    const int r    = threadIdx.x >> 6;
    const int lane = threadIdx.x & 63;
    const size_t row = (size_t)blockIdx.x * 4 + r;

    sx[r][lane] = x[row * NDIM + lane];
    sd[r][lane] = diag[row * NDIM + lane];
    const float* offr = off + row * OFFDIM;
    for (int i = lane; i < OFFDIM; i += 64) soff[r][i] = offr[i];
    __syncthreads();

    float v = sd[r][lane] * sx[r][lane];
    for (int i = lane + 1; i < NDIM; i++)
        v += soff[r][i * (i - 1) / 2 + lane] * sx[r][i];
    sv[r][lane] = v;
    __syncthreads();

    float o = sd[r][lane] * v;
    const int base = lane * (lane - 1) / 2;
    for (int j = 0; j < lane; j++) o += soff[r][base + j] * sv[r][j];
    out[row * NDIM + lane] = o;
}

// ---------------------------------------------------------------------------
// Launch. Order: prep_w(1), prep_x(2), L1(3), L2-batched(4), diag(5),
// Woo(6) — ncu -s 5 -c 1 captures the dominant Woo GEMM — final(7).
// ---------------------------------------------------------------------------
extern "C" void kernel_launch(void* const* d_in, const int* in_sizes, int n_in,
                              void* d_out, int out_size) {
    const float* x    = (const float*)d_in[0];
    const float* Wd1  = (const float*)d_in[1];
    const float* bd1  = (const float*)d_in[2];
    const float* Wd2  = (const float*)d_in[3];
    const float* bd2  = (const float*)d_in[4];
    const float* Wdo  = (const float*)d_in[5];
    const float* bdo  = (const float*)d_in[6];
    const float* Wo1  = (const float*)d_in[7];
    const float* bo1  = (const float*)d_in[8];
    const float* Wo2  = (const float*)d_in[9];
    const float* bo2  = (const float*)d_in[10];
    const float* Woo  = (const float*)d_in[11];
    const float* boo  = (const float*)d_in[12];
    const float* dmin = (const float*)d_in[13];
    float* out = (float*)d_out;

    float *h1, *h2, *h3, *dg, *off, *b1;
    __nv_bfloat16 *wt, *xs;
    cudaGetSymbolAddress((void**)&h1,  g_h1);
    cudaGetSymbolAddress((void**)&h2,  g_h2);
    cudaGetSymbolAddress((void**)&h3,  g_h3);
    cudaGetSymbolAddress((void**)&dg,  g_diag);
    cudaGetSymbolAddress((void**)&off, g_off);
    cudaGetSymbolAddress((void**)&wt,  g_wt);
    cudaGetSymbolAddress((void**)&xs,  g_xs);
    cudaGetSymbolAddress((void**)&b1,  g_b1);

    cudaFuncSetAttribute(gemm_mma<EPI_TANH>,
                         cudaFuncAttributeMaxDynamicSharedMemorySize, GEMM_SMEM);
    cudaFuncSetAttribute(gemm_mma<EPI_BIAS>,
                         cudaFuncAttributeMaxDynamicSharedMemorySize, GEMM_SMEM);
    cudaFuncSetAttribute(gemm_mma<EPI_DIAG>,
                         cudaFuncAttributeMaxDynamicSharedMemorySize, GEMM_SMEM);

    const int MB = B_ROWS / BM;  // 128 m-tiles

    // 1-2: prep (weights + concat bias; x split)
    prep_w<<<(WT_TOT + 255) / 256, 256>>>(Wd1, Wd2, Wdo, Wo1, Wo2, Woo,
                                          bd1, bo1, wt, b1);
    prep_x<<<(B_ROWS * NDIM) / 256, 256>>>(x, xs);

    // 3: layer-1 merged (K=64, N=512) -> h1 [M][512 split-chunk]
    gemm_mma<EPI_TANH><<<dim3(4, MB), NTHR, GEMM_SMEM>>>(
        xs, xs, wt + 2 * WT_L1, wt + 2 * WT_L1, b1, b1, (char*)h1, (char*)h1,
        64, 64, 512, 512, nullptr, nullptr);

    // 4: layer-2 batched (z=0: h1[:,0:256]@Wd2 -> h2;
    //                     z=1: h1[:,256:512]@Wo2 -> h3)
    gemm_mma<EPI_TANH><<<dim3(2, MB, 2), NTHR, GEMM_SMEM>>>(
        (const __nv_bfloat16*)h1, (const __nv_bfloat16*)h1 + 512,
        wt + 2 * WT_D2, wt + 2 * WT_O2, bd2, bo2, (char*)h2, (char*)h3,
        512, HDIM, HDIM, HDIM, nullptr, nullptr);

    // 5: diag output (K=256, N=64) -> dg fp32
    gemm_mma<EPI_DIAG><<<dim3(1, MB), NTHR, GEMM_SMEM>>>(
        (const __nv_bfloat16*)h2, (const __nv_bfloat16*)h2,
        wt + 2 * WT_DO, wt + 2 * WT_DO, bdo, bdo, (char*)dg, (char*)dg,
        HDIM, HDIM, NDIM, NDIM, x, dmin);

    // 6: dominant Woo GEMM (K=256, N=2016) -> off fp32 (ncu captures this)
    gemm_mma<EPI_BIAS><<<dim3(16, MB), NTHR, GEMM_SMEM>>>(
        (const __nv_bfloat16*)h3, (const __nv_bfloat16*)h3,
        wt + 2 * WT_OO, wt + 2 * WT_OO, boo, boo, (char*)off, (char*)off,
        HDIM, HDIM, OFFDIM, OFFDIM, nullptr, nullptr);

    // 7: L (L^T x)
    final_kernel<<<B_ROWS / 4, 256>>>(off, dg, x, out);
}